// round 1
// baseline (speedup 1.0000x reference)
#include <cuda_runtime.h>
#include <math.h>

#define B_  64
#define N_  512
#define D_  256
#define H_  8
#define DK_ 32
#define M_  (B_*N_)   // 32768

// ---------------- scratch (static device globals; no allocation) ----------
__device__ __align__(256) float g_q[M_*D_];
__device__ __align__(256) float g_k[M_*D_];
__device__ __align__(256) float g_v[M_*D_];
__device__ __align__(256) float g_ao[M_*D_];
__device__ unsigned char g_inv[M_];

// ---------------- mask precompute -----------------------------------------
__global__ void mask_kernel(const int* __restrict__ mask,
                            const int* __restrict__ ncount) {
    int idx = blockIdx.x * 256 + threadIdx.x;
    if (idx < M_) {
        int b = idx >> 9;
        int n = idx & 511;
        bool inv = (mask[2*idx] != 0) || (mask[2*idx+1] != 0) || (n >= ncount[b]);
        g_inv[idx] = inv ? 1 : 0;
    }
}

// ---------------- fp32 GEMM: C[M x 256] = A[M x 256] @ W[256 x 256] + bias (+res)
// BM=128, BN=128, BK=16, 256 threads, 8x8 thread tile
template<bool RES>
__device__ __forceinline__ void gemm_body(const float* __restrict__ A,
                                          const float* __restrict__ W,
                                          const float* __restrict__ bias,
                                          const float* __restrict__ res,
                                          float* __restrict__ C) {
    __shared__ float As[16][132];   // k-major, padded (132*4B = 16B-aligned rows)
    __shared__ float Bs[16][128];

    const int tid = threadIdx.x;
    const int tx = tid & 15;
    const int ty = tid >> 4;
    const int row0 = blockIdx.x * 128;
    const int col0 = blockIdx.y * 128;

    float acc[8][8];
#pragma unroll
    for (int i = 0; i < 8; i++)
#pragma unroll
        for (int j = 0; j < 8; j++) acc[i][j] = 0.f;

    const int ar = tid >> 2;          // 0..63
    const int ac = (tid & 3) << 2;    // 0,4,8,12
    const int br = tid >> 5;          // 0..7
    const int bc = (tid & 31) << 2;   // 0..124

    for (int kk = 0; kk < 256; kk += 16) {
#pragma unroll
        for (int p = 0; p < 2; p++) {
            float4 a = *(const float4*)&A[(size_t)(row0 + ar + p*64)*D_ + kk + ac];
            As[ac+0][ar + p*64] = a.x;
            As[ac+1][ar + p*64] = a.y;
            As[ac+2][ar + p*64] = a.z;
            As[ac+3][ar + p*64] = a.w;
            *(float4*)&Bs[br + p*8][bc] =
                *(const float4*)&W[(size_t)(kk + br + p*8)*D_ + col0 + bc];
        }
        __syncthreads();
#pragma unroll
        for (int k = 0; k < 16; k++) {
            float ra[8], rb[8];
            *(float4*)&ra[0] = *(const float4*)&As[k][ty*8];
            *(float4*)&ra[4] = *(const float4*)&As[k][ty*8 + 4];
            *(float4*)&rb[0] = *(const float4*)&Bs[k][tx*8];
            *(float4*)&rb[4] = *(const float4*)&Bs[k][tx*8 + 4];
#pragma unroll
            for (int i = 0; i < 8; i++)
#pragma unroll
                for (int j = 0; j < 8; j++)
                    acc[i][j] = fmaf(ra[i], rb[j], acc[i][j]);
        }
        __syncthreads();
    }

#pragma unroll
    for (int i = 0; i < 8; i++) {
        const int r = row0 + ty*8 + i;
#pragma unroll
        for (int j = 0; j < 8; j += 4) {
            const int c = col0 + tx*8 + j;
            float4 o;
            o.x = acc[i][j+0] + bias[c+0];
            o.y = acc[i][j+1] + bias[c+1];
            o.z = acc[i][j+2] + bias[c+2];
            o.w = acc[i][j+3] + bias[c+3];
            if (RES) {
                const float4 rr = *(const float4*)&res[(size_t)r*D_ + c];
                o.x += rr.x; o.y += rr.y; o.z += rr.z; o.w += rr.w;
            }
            *(float4*)&C[(size_t)r*D_ + c] = o;
        }
    }
}

__global__ void __launch_bounds__(256, 2)
qkv_kernel(const float* __restrict__ A,
           const float* __restrict__ Wq, const float* __restrict__ bq,
           const float* __restrict__ Wk, const float* __restrict__ bk,
           const float* __restrict__ Wv, const float* __restrict__ bv) {
    const int z = blockIdx.z;
    const float* W  = (z == 0) ? Wq : (z == 1) ? Wk : Wv;
    const float* bb = (z == 0) ? bq : (z == 1) ? bk : bv;
    float* C        = (z == 0) ? g_q : (z == 1) ? g_k : g_v;
    gemm_body<false>(A, W, bb, nullptr, C);
}

__global__ void __launch_bounds__(256, 2)
oproj_kernel(const float* __restrict__ Wo, const float* __restrict__ bo,
             const float* __restrict__ hres, float* __restrict__ out) {
    gemm_body<true>(g_ao, Wo, bo, hres, out);
}

// ---------------- fused attention ------------------------------------------
// One block per (b, h). 256 threads. Full 512x? score rows staged in smem
// (stored key-major so they are already k-major for the P@V GEMM).
struct AttnSmem {
    float S[512][68];                           // S[key][qr], qr in qtile of 64
    float Q[32][68];                            // Q k-major: Q[dk][qr]
    union {
        float K[32][132];                       // K chunk k-major: K[dk][key_local]
        float V[128][36];                       // V chunk row-major: V[key_local][dk]
    } kv;
    float red[4][64];
    float rowmax[64];
    float rowsum[64];
    unsigned char inv[512];
};

__global__ void __launch_bounds__(256, 1)
attn_kernel() {
    extern __shared__ char smem_raw[];
    AttnSmem& sm = *reinterpret_cast<AttnSmem*>(smem_raw);

    const int tid = threadIdx.x;
    const int tx = tid & 15;
    const int ty = tid >> 4;
    const int b  = blockIdx.x >> 3;
    const int hh = blockIdx.x & 7;

    const float* Qg = g_q  + (size_t)b*N_*D_ + hh*DK_;
    const float* Kg = g_k  + (size_t)b*N_*D_ + hh*DK_;
    const float* Vg = g_v  + (size_t)b*N_*D_ + hh*DK_;
    float*       Og = g_ao + (size_t)b*N_*D_ + hh*DK_;

    sm.inv[tid]       = g_inv[b*N_ + tid];
    sm.inv[tid + 256] = g_inv[b*N_ + tid + 256];

    const float rscale = 0.17677669529663689f;  // 1/sqrt(32)

    for (int q0 = 0; q0 < N_; q0 += 64) {
        // ---- load Q tile (64 x 32), transposed to k-major ----
        {
            const int qr = tid >> 3;            // 0..31
            const int cg = (tid & 7) << 2;      // 0,4,...,28
#pragma unroll
            for (int p = 0; p < 2; p++) {
                float4 v = *(const float4*)&Qg[(size_t)(q0 + qr + p*32)*D_ + cg];
                sm.Q[cg+0][qr + p*32] = v.x;
                sm.Q[cg+1][qr + p*32] = v.y;
                sm.Q[cg+2][qr + p*32] = v.z;
                sm.Q[cg+3][qr + p*32] = v.w;
            }
        }

        // ---- phase 1: S = Q @ K^T, masked, over key chunks of 128 ----
        for (int kc0 = 0; kc0 < N_; kc0 += 128) {
            __syncthreads();  // K/V buffer free + Q visible after next sync
            {
                const int cg = (tid & 7) << 2;
#pragma unroll
                for (int p = 0; p < 4; p++) {
                    int kl = (tid >> 3) + p*32;     // 0..127
                    float4 v = *(const float4*)&Kg[(size_t)(kc0 + kl)*D_ + cg];
                    sm.kv.K[cg+0][kl] = v.x;
                    sm.kv.K[cg+1][kl] = v.y;
                    sm.kv.K[cg+2][kl] = v.z;
                    sm.kv.K[cg+3][kl] = v.w;
                }
            }
            __syncthreads();

            float accS[4][8];
#pragma unroll
            for (int i = 0; i < 4; i++)
#pragma unroll
                for (int j = 0; j < 8; j++) accS[i][j] = 0.f;

#pragma unroll
            for (int k = 0; k < 32; k++) {
                float4 q4 = *(const float4*)&sm.Q[k][ty*4];
                float qa[4] = {q4.x, q4.y, q4.z, q4.w};
                float kr[8];
#pragma unroll
                for (int jj = 0; jj < 8; jj++) kr[jj] = sm.kv.K[k][tx + 16*jj];
#pragma unroll
                for (int i = 0; i < 4; i++)
#pragma unroll
                    for (int jj = 0; jj < 8; jj++)
                        accS[i][jj] = fmaf(qa[i], kr[jj], accS[i][jj]);
            }

            bool iq[4];
#pragma unroll
            for (int i = 0; i < 4; i++) iq[i] = sm.inv[q0 + ty*4 + i] != 0;
#pragma unroll
            for (int jj = 0; jj < 8; jj++) {
                const int key = kc0 + tx + 16*jj;
                const bool ik = sm.inv[key] != 0;
                float4 sv;
                sv.x = (ik || iq[0]) ? -1e9f : accS[0][jj] * rscale;
                sv.y = (ik || iq[1]) ? -1e9f : accS[1][jj] * rscale;
                sv.z = (ik || iq[2]) ? -1e9f : accS[2][jj] * rscale;
                sv.w = (ik || iq[3]) ? -1e9f : accS[3][jj] * rscale;
                *(float4*)&sm.S[key][ty*4] = sv;  // conflict-free: lanes hit distinct banks
            }
        }
        __syncthreads();

        // ---- phase 2: row softmax (64 rows x 512 keys) ----
        {
            const int r    = tid & 63;
            const int part = tid >> 6;          // 0..3, keys [part*128, +128)
            float m = -INFINITY;
            for (int k = part*128; k < part*128 + 128; k++)
                m = fmaxf(m, sm.S[k][r]);
            sm.red[part][r] = m;
            __syncthreads();
            if (tid < 64) {
                sm.rowmax[tid] = fmaxf(fmaxf(sm.red[0][tid], sm.red[1][tid]),
                                       fmaxf(sm.red[2][tid], sm.red[3][tid]));
            }
            __syncthreads();
            const float rm = sm.rowmax[r];
            float s = 0.f;
            for (int k = part*128; k < part*128 + 128; k++) {
                float e = __expf(sm.S[k][r] - rm);
                sm.S[k][r] = e;
                s += e;
            }
            sm.red[part][r] = s;
            __syncthreads();
            if (tid < 64) {
                sm.rowsum[tid] = sm.red[0][tid] + sm.red[1][tid]
                               + sm.red[2][tid] + sm.red[3][tid];
            }
        }

        // ---- phase 3: O = P @ V over key chunks of 128 ----
        float accO[4][2];
#pragma unroll
        for (int i = 0; i < 4; i++) { accO[i][0] = 0.f; accO[i][1] = 0.f; }

        for (int kc0 = 0; kc0 < N_; kc0 += 128) {
            __syncthreads();  // rowsum/S writes visible; prior V consumed
            {
                const int cg = (tid & 7) << 2;
#pragma unroll
                for (int p = 0; p < 4; p++) {
                    int kl = (tid >> 3) + p*32;
                    *(float4*)&sm.kv.V[kl][cg] =
                        *(const float4*)&Vg[(size_t)(kc0 + kl)*D_ + cg];
                }
            }
            __syncthreads();
#pragma unroll 4
            for (int kk = 0; kk < 128; kk++) {
                float4 p4 = *(const float4*)&sm.S[kc0 + kk][ty*4];
                float2 v2 = *(const float2*)&sm.kv.V[kk][tx*2];
                accO[0][0] = fmaf(p4.x, v2.x, accO[0][0]);
                accO[0][1] = fmaf(p4.x, v2.y, accO[0][1]);
                accO[1][0] = fmaf(p4.y, v2.x, accO[1][0]);
                accO[1][1] = fmaf(p4.y, v2.y, accO[1][1]);
                accO[2][0] = fmaf(p4.z, v2.x, accO[2][0]);
                accO[2][1] = fmaf(p4.z, v2.y, accO[2][1]);
                accO[3][0] = fmaf(p4.w, v2.x, accO[3][0]);
                accO[3][1] = fmaf(p4.w, v2.y, accO[3][1]);
            }
        }
        __syncthreads();

        // ---- epilogue: normalize and store ----
#pragma unroll
        for (int i = 0; i < 4; i++) {
            const float rs = 1.0f / sm.rowsum[ty*4 + i];
            const int qr = q0 + ty*4 + i;
            Og[(size_t)qr*D_ + tx*2 + 0] = accO[i][0] * rs;
            Og[(size_t)qr*D_ + tx*2 + 1] = accO[i][1] * rs;
        }
    }
}

// ---------------- launcher --------------------------------------------------
extern "C" void kernel_launch(void* const* d_in, const int* in_sizes, int n_in,
                              void* d_out, int out_size) {
    const float* h    = (const float*)d_in[0];
    const int*   mask = (const int*)  d_in[1];
    const int*   nc   = (const int*)  d_in[2];
    const float* Wq   = (const float*)d_in[3];
    const float* bq   = (const float*)d_in[4];
    const float* Wk   = (const float*)d_in[5];
    const float* bk   = (const float*)d_in[6];
    const float* Wv   = (const float*)d_in[7];
    const float* bv   = (const float*)d_in[8];
    const float* Wo   = (const float*)d_in[9];
    const float* bo   = (const float*)d_in[10];
    float* out = (float*)d_out;

    cudaFuncSetAttribute(attn_kernel, cudaFuncAttributeMaxDynamicSharedMemorySize,
                         (int)sizeof(AttnSmem));

    mask_kernel<<<M_/256, 256>>>(mask, nc);
    qkv_kernel<<<dim3(M_/128, D_/128, 3), 256>>>(h, Wq, bq, Wk, bk, Wv, bv);
    attn_kernel<<<B_*H_, 256, (int)sizeof(AttnSmem)>>>();
    oproj_kernel<<<dim3(M_/128, D_/128), 256>>>(Wo, bo, h, out);
}

// round 2
// speedup vs baseline: 2.7157x; 2.7157x over previous
#include <cuda_runtime.h>
#include <math.h>
#include <stdint.h>

#define B_  64
#define N_  512
#define D_  256
#define H_  8
#define DK_ 32
#define M_  (B_*N_)   // 32768

// ---------------- scratch (static device globals; no allocation) ----------
__device__ __align__(256) float g_q[M_*D_];
__device__ __align__(256) float g_k[M_*D_];
__device__ __align__(256) float g_v[M_*D_];
__device__ __align__(256) float g_ao[M_*D_];
__device__ unsigned char g_inv[M_];

// ---------------- helpers ---------------------------------------------------
__device__ __forceinline__ float to_tf32(float x) {
    uint32_t r;
    asm("cvt.rna.tf32.f32 %0, %1;" : "=r"(r) : "f"(x));
    return __uint_as_float(r);
}
__device__ __forceinline__ float4 tf32x4(float4 v) {
    return make_float4(to_tf32(v.x), to_tf32(v.y), to_tf32(v.z), to_tf32(v.w));
}
// D += A(16x8 tf32, row) * B(8x8 tf32, col)
__device__ __forceinline__ void mma_tf32(float* d, const uint32_t* a, const uint32_t* b) {
    asm volatile(
        "mma.sync.aligned.m16n8k8.row.col.f32.tf32.tf32.f32 "
        "{%0,%1,%2,%3}, {%4,%5,%6,%7}, {%8,%9}, {%0,%1,%2,%3};\n"
        : "+f"(d[0]), "+f"(d[1]), "+f"(d[2]), "+f"(d[3])
        : "r"(a[0]), "r"(a[1]), "r"(a[2]), "r"(a[3]), "r"(b[0]), "r"(b[1]));
}

// ---------------- mask precompute -------------------------------------------
__global__ void mask_kernel(const int* __restrict__ mask,
                            const int* __restrict__ ncount) {
    int idx = blockIdx.x * 256 + threadIdx.x;
    if (idx < M_) {
        int b = idx >> 9;
        int n = idx & 511;
        bool inv = (mask[2*idx] != 0) || (mask[2*idx+1] != 0) || (n >= ncount[b]);
        g_inv[idx] = inv ? 1 : 0;
    }
}

// ---------------- tf32 mma GEMM: C[Mx256] = A[Mx256] @ W[256x256] (+bias,+res)
// block 128x128, BK=32, 256 threads, 8 warps of 32x64 (2 m-atoms x 8 n-atoms)
template<bool RES>
__device__ __forceinline__ void gemm_mma(const float* __restrict__ A,
                                         const float* __restrict__ W,
                                         const float* __restrict__ bias,
                                         const float* __restrict__ res,
                                         float* __restrict__ C) {
    __shared__ float As[128*36];   // row-major [m][32+4]: frag bank = 4g+t (cf-free)
    __shared__ float Bs[32*136];   // row-major [k][128+8]: frag bank = 8t+g (cf-free)

    const int tid  = threadIdx.x;
    const int lane = tid & 31, warp = tid >> 5;
    const int g = lane >> 2, t = lane & 3;
    const int mw = (warp >> 1) * 32, nw = (warp & 1) * 64;
    const int row0 = blockIdx.x * 128, col0 = blockIdx.y * 128;

    float acc[2][8][4];
#pragma unroll
    for (int i = 0; i < 2; i++)
#pragma unroll
        for (int j = 0; j < 8; j++)
#pragma unroll
            for (int q = 0; q < 4; q++) acc[i][j][q] = 0.f;

    const int ar = tid >> 3, ac = (tid & 7) * 4;    // A loader: 128x32 tile
    const int br = tid >> 5, bc = (tid & 31) * 4;   // B loader: 32x128 tile

    float4 pa[4], pb[4];
#pragma unroll
    for (int p = 0; p < 4; p++) {
        pa[p] = *(const float4*)&A[(size_t)(row0 + ar + 32*p)*D_ + ac];
        pb[p] = *(const float4*)&W[(size_t)(br + 8*p)*D_ + col0 + bc];
    }

    for (int kk = 0; kk < 256; kk += 32) {
        __syncthreads();   // previous compute finished reading smem
#pragma unroll
        for (int p = 0; p < 4; p++) {
            *(float4*)&As[(ar + 32*p)*36 + ac]  = tf32x4(pa[p]);
            *(float4*)&Bs[(br + 8*p)*136 + bc] = tf32x4(pb[p]);
        }
        __syncthreads();
        if (kk + 32 < 256) {
#pragma unroll
            for (int p = 0; p < 4; p++) {
                pa[p] = *(const float4*)&A[(size_t)(row0 + ar + 32*p)*D_ + kk + 32 + ac];
                pb[p] = *(const float4*)&W[(size_t)(kk + 32 + br + 8*p)*D_ + col0 + bc];
            }
        }
#pragma unroll
        for (int ks = 0; ks < 4; ks++) {
            const int k = ks * 8;
            uint32_t af[2][4];
#pragma unroll
            for (int ma = 0; ma < 2; ma++) {
                const float* ab = &As[(mw + ma*16 + g)*36 + k + t];
                af[ma][0] = __float_as_uint(ab[0]);
                af[ma][1] = __float_as_uint(ab[8*36]);
                af[ma][2] = __float_as_uint(ab[4]);
                af[ma][3] = __float_as_uint(ab[8*36 + 4]);
            }
#pragma unroll
            for (int na = 0; na < 8; na++) {
                const float* bb = &Bs[(k + t)*136 + nw + na*8 + g];
                uint32_t bf[2] = {__float_as_uint(bb[0]), __float_as_uint(bb[4*136])};
                mma_tf32(acc[0][na], af[0], bf);
                mma_tf32(acc[1][na], af[1], bf);
            }
        }
    }

#pragma unroll
    for (int ma = 0; ma < 2; ma++) {
        const int r0g = row0 + mw + ma*16 + g;
#pragma unroll
        for (int na = 0; na < 8; na++) {
            const int c0 = col0 + nw + na*8 + 2*t;
            float2 o0, o1;
            o0.x = acc[ma][na][0] + bias[c0];
            o0.y = acc[ma][na][1] + bias[c0+1];
            o1.x = acc[ma][na][2] + bias[c0];
            o1.y = acc[ma][na][3] + bias[c0+1];
            if (RES) {
                float2 ra = *(const float2*)&res[(size_t)r0g*D_ + c0];
                float2 rb = *(const float2*)&res[(size_t)(r0g+8)*D_ + c0];
                o0.x += ra.x; o0.y += ra.y;
                o1.x += rb.x; o1.y += rb.y;
            }
            *(float2*)&C[(size_t)r0g*D_ + c0]     = o0;
            *(float2*)&C[(size_t)(r0g+8)*D_ + c0] = o1;
        }
    }
}

__global__ void __launch_bounds__(256, 2)
qkv_kernel(const float* __restrict__ A,
           const float* __restrict__ Wq, const float* __restrict__ bq,
           const float* __restrict__ Wk, const float* __restrict__ bk,
           const float* __restrict__ Wv, const float* __restrict__ bv) {
    const int z = blockIdx.z;
    const float* W  = (z == 0) ? Wq : (z == 1) ? Wk : Wv;
    const float* bb = (z == 0) ? bq : (z == 1) ? bk : bv;
    float* C        = (z == 0) ? g_q : (z == 1) ? g_k : g_v;
    gemm_mma<false>(A, W, bb, nullptr, C);
}

__global__ void __launch_bounds__(256, 2)
oproj_kernel(const float* __restrict__ Wo, const float* __restrict__ bo,
             const float* __restrict__ hres, float* __restrict__ out) {
    gemm_mma<true>(g_ao, Wo, bo, hres, out);
}

// ---------------- fused attention (tf32 mma, K/V resident in smem) ----------
// One block per (b,h), 256 threads / 8 warps.
// smem floats: Qs[32][36] | Ks[512][36] | Vs[512][40] | Ss[32][524] | rsum[32] | inv[512]B
#define OFF_Q  0
#define OFF_K  1152
#define OFF_V  19584
#define OFF_S  40064
#define OFF_RS 56832
#define ATTN_SMEM_BYTES (56864*4 + 512)   // 227,968 B

__global__ void __launch_bounds__(256, 1)
attn_kernel() {
    extern __shared__ float sm[];
    float* Qs   = sm + OFF_Q;
    float* Ks   = sm + OFF_K;
    float* Vs   = sm + OFF_V;
    float* Ss   = sm + OFF_S;
    float* rsum = sm + OFF_RS;
    unsigned char* sinv = (unsigned char*)(sm + 56864);

    const int tid  = threadIdx.x;
    const int lane = tid & 31, warp = tid >> 5;
    const int g = lane >> 2, t = lane & 3;
    const int b  = blockIdx.x >> 3;
    const int hh = blockIdx.x & 7;

    const float* Qg = g_q  + (size_t)b*N_*D_ + hh*DK_;
    const float* Kg = g_k  + (size_t)b*N_*D_ + hh*DK_;
    const float* Vg = g_v  + (size_t)b*N_*D_ + hh*DK_;
    float*       Og = g_ao + (size_t)b*N_*D_ + hh*DK_;

    sinv[tid]       = g_inv[b*N_ + tid];
    sinv[tid + 256] = g_inv[b*N_ + tid + 256];

    // ---- load K and V fully into smem (tf32-rounded) ----
    {
        const int r = tid >> 3, c = (tid & 7) * 4;
#pragma unroll
        for (int p = 0; p < 16; p++) {
            const int key = r + 32*p;
            float4 kv = *(const float4*)&Kg[(size_t)key*D_ + c];
            *(float4*)&Ks[key*36 + c] = tf32x4(kv);
            float4 vv = *(const float4*)&Vg[(size_t)key*D_ + c];
            *(float4*)&Vs[key*40 + c] = tf32x4(vv);
        }
    }
    __syncthreads();

    const float rscale = 0.17677669529663689f;  // 1/sqrt(32)

    for (int q0 = 0; q0 < N_; q0 += 32) {
        // ---- load Q tile 32x32 ----
        {
            const int r = tid >> 3, c = (tid & 7) * 4;
            float4 qv = *(const float4*)&Qg[(size_t)(q0 + r)*D_ + c];
            *(float4*)&Qs[r*36 + c] = tf32x4(qv);
        }
        __syncthreads();

        // ---- phase 1: S = Q @ K^T ; warp w covers keys [64w, 64w+64) ----
        {
            const int nw = warp * 64;
            float acc[2][8][4];
#pragma unroll
            for (int i = 0; i < 2; i++)
#pragma unroll
                for (int j = 0; j < 8; j++)
#pragma unroll
                    for (int q = 0; q < 4; q++) acc[i][j][q] = 0.f;

#pragma unroll
            for (int ks = 0; ks < 4; ks++) {
                const int k = ks * 8;
                uint32_t af[2][4];
#pragma unroll
                for (int ma = 0; ma < 2; ma++) {
                    const float* ab = &Qs[(ma*16 + g)*36 + k + t];
                    af[ma][0] = __float_as_uint(ab[0]);
                    af[ma][1] = __float_as_uint(ab[8*36]);
                    af[ma][2] = __float_as_uint(ab[4]);
                    af[ma][3] = __float_as_uint(ab[8*36 + 4]);
                }
#pragma unroll
                for (int na = 0; na < 8; na++) {
                    const float* bb = &Ks[(nw + na*8 + g)*36 + k + t];
                    uint32_t bf[2] = {__float_as_uint(bb[0]), __float_as_uint(bb[4])};
                    mma_tf32(acc[0][na], af[0], bf);
                    mma_tf32(acc[1][na], af[1], bf);
                }
            }
            // epilogue: scale + mask -> Ss
#pragma unroll
            for (int ma = 0; ma < 2; ma++) {
                const int r0 = ma*16 + g;
                const bool iqa = sinv[q0 + r0] != 0;
                const bool iqb = sinv[q0 + r0 + 8] != 0;
#pragma unroll
                for (int na = 0; na < 8; na++) {
                    const int col = nw + na*8 + 2*t;
                    const bool ik0 = sinv[col] != 0;
                    const bool ik1 = sinv[col + 1] != 0;
                    float2 s0, s1;
                    s0.x = (iqa || ik0) ? -1e9f : acc[ma][na][0] * rscale;
                    s0.y = (iqa || ik1) ? -1e9f : acc[ma][na][1] * rscale;
                    s1.x = (iqb || ik0) ? -1e9f : acc[ma][na][2] * rscale;
                    s1.y = (iqb || ik1) ? -1e9f : acc[ma][na][3] * rscale;
                    *(float2*)&Ss[r0*524 + col]     = s0;
                    *(float2*)&Ss[(r0+8)*524 + col] = s1;
                }
            }
        }
        __syncthreads();

        // ---- phase 2: softmax over 512 keys, 8 threads per row ----
        {
            const int r  = tid >> 3;
            const int sg = tid & 7;
            float* srow = &Ss[r*524 + sg*4];   // cols sg*4 + 32*i (bank-spread)
            float m = -1e30f;
#pragma unroll
            for (int i = 0; i < 16; i++) {
                float4 v = *(float4*)&srow[i*32];
                m = fmaxf(m, fmaxf(fmaxf(v.x, v.y), fmaxf(v.z, v.w)));
            }
            m = fmaxf(m, __shfl_xor_sync(0xffffffffu, m, 1));
            m = fmaxf(m, __shfl_xor_sync(0xffffffffu, m, 2));
            m = fmaxf(m, __shfl_xor_sync(0xffffffffu, m, 4));
            float s = 0.f;
#pragma unroll
            for (int i = 0; i < 16; i++) {
                float4 v = *(float4*)&srow[i*32];
                v.x = __expf(v.x - m); v.y = __expf(v.y - m);
                v.z = __expf(v.z - m); v.w = __expf(v.w - m);
                *(float4*)&srow[i*32] = v;
                s += v.x + v.y + v.z + v.w;
            }
            s += __shfl_xor_sync(0xffffffffu, s, 1);
            s += __shfl_xor_sync(0xffffffffu, s, 2);
            s += __shfl_xor_sync(0xffffffffu, s, 4);
            if ((tid & 7) == 0) rsum[r] = s;
        }
        __syncthreads();

        // ---- phase 3: O = P @ V ; warp w accumulates keys [64w, 64w+64) ----
        {
            const int kw = warp * 64;
            float acc[2][4][4];
#pragma unroll
            for (int i = 0; i < 2; i++)
#pragma unroll
                for (int j = 0; j < 4; j++)
#pragma unroll
                    for (int q = 0; q < 4; q++) acc[i][j][q] = 0.f;

#pragma unroll
            for (int ks = 0; ks < 8; ks++) {
                const int k = kw + ks*8;
                uint32_t af[2][4];
#pragma unroll
                for (int ma = 0; ma < 2; ma++) {
                    const float* ab = &Ss[(ma*16 + g)*524 + k + t];
                    af[ma][0] = __float_as_uint(ab[0]);
                    af[ma][1] = __float_as_uint(ab[8*524]);
                    af[ma][2] = __float_as_uint(ab[4]);
                    af[ma][3] = __float_as_uint(ab[8*524 + 4]);
                }
#pragma unroll
                for (int na = 0; na < 4; na++) {
                    const float* bb = &Vs[(k + t)*40 + na*8 + g];
                    uint32_t bf[2] = {__float_as_uint(bb[0]), __float_as_uint(bb[4*40])};
                    mma_tf32(acc[0][na], af[0], bf);
                    mma_tf32(acc[1][na], af[1], bf);
                }
            }
            __syncthreads();   // all warps done reading P before overwrite
            // write partials into Ss region: Opart[w][32][36]
            float* op = Ss + warp * 1152;
#pragma unroll
            for (int ma = 0; ma < 2; ma++) {
                const int r0 = ma*16 + g;
#pragma unroll
                for (int na = 0; na < 4; na++) {
                    const int col = na*8 + 2*t;
                    float2 p0 = {acc[ma][na][0], acc[ma][na][1]};
                    float2 p1 = {acc[ma][na][2], acc[ma][na][3]};
                    *(float2*)&op[r0*36 + col]     = p0;
                    *(float2*)&op[(r0+8)*36 + col] = p1;
                }
            }
        }
        __syncthreads();

        // ---- reduce 8 partials, normalize, store ----
        {
            const int q  = tid >> 3;
            const int c4 = (tid & 7) * 4;
            float4 o = {0.f, 0.f, 0.f, 0.f};
#pragma unroll
            for (int w = 0; w < 8; w++) {
                float4 p = *(float4*)&Ss[w*1152 + q*36 + c4];
                o.x += p.x; o.y += p.y; o.z += p.z; o.w += p.w;
            }
            const float rs = 1.0f / rsum[q];
            o.x *= rs; o.y *= rs; o.z *= rs; o.w *= rs;
            *(float4*)&Og[(size_t)(q0 + q)*D_ + c4] = o;
        }
        __syncthreads();
    }
}

// ---------------- launcher --------------------------------------------------
extern "C" void kernel_launch(void* const* d_in, const int* in_sizes, int n_in,
                              void* d_out, int out_size) {
    const float* h    = (const float*)d_in[0];
    const int*   mask = (const int*)  d_in[1];
    const int*   nc   = (const int*)  d_in[2];
    const float* Wq   = (const float*)d_in[3];
    const float* bq   = (const float*)d_in[4];
    const float* Wk   = (const float*)d_in[5];
    const float* bk   = (const float*)d_in[6];
    const float* Wv   = (const float*)d_in[7];
    const float* bv   = (const float*)d_in[8];
    const float* Wo   = (const float*)d_in[9];
    const float* bo   = (const float*)d_in[10];
    float* out = (float*)d_out;

    cudaFuncSetAttribute(attn_kernel, cudaFuncAttributeMaxDynamicSharedMemorySize,
                         ATTN_SMEM_BYTES);

    mask_kernel<<<M_/256, 256>>>(mask, nc);
    qkv_kernel<<<dim3(M_/128, D_/128, 3), 256>>>(h, Wq, bq, Wk, bk, Wv, bv);
    attn_kernel<<<B_*H_, 256, ATTN_SMEM_BYTES>>>();
    oproj_kernel<<<dim3(M_/128, D_/128), 256>>>(Wo, bo, h, out);
}

// round 3
// speedup vs baseline: 2.7808x; 1.0240x over previous
#include <cuda_runtime.h>
#include <math.h>
#include <stdint.h>

#define B_  64
#define N_  512
#define D_  256
#define H_  8
#define DK_ 32
#define M_  (B_*N_)   // 32768

// ---------------- scratch (static device globals; no allocation) ----------
__device__ __align__(256) float g_q[M_*D_];
__device__ __align__(256) float g_k[M_*D_];
__device__ __align__(256) float g_v[M_*D_];
__device__ __align__(256) float g_ao[M_*D_];
__device__ __align__(256) float g_wr[4*D_*D_];   // tf32-rounded Wq,Wk,Wv,Wo
__device__ unsigned char g_inv[M_];

// ---------------- helpers ---------------------------------------------------
__device__ __forceinline__ float to_tf32(float x) {
    uint32_t r;
    asm("cvt.rna.tf32.f32 %0, %1;" : "=r"(r) : "f"(x));
    return __uint_as_float(r);
}
__device__ __forceinline__ float4 tf32x4(float4 v) {
    return make_float4(to_tf32(v.x), to_tf32(v.y), to_tf32(v.z), to_tf32(v.w));
}
__device__ __forceinline__ void mma_tf32(float* d, const uint32_t* a, const uint32_t* b) {
    asm volatile(
        "mma.sync.aligned.m16n8k8.row.col.f32.tf32.tf32.f32 "
        "{%0,%1,%2,%3}, {%4,%5,%6,%7}, {%8,%9}, {%0,%1,%2,%3};\n"
        : "+f"(d[0]), "+f"(d[1]), "+f"(d[2]), "+f"(d[3])
        : "r"(a[0]), "r"(a[1]), "r"(a[2]), "r"(a[3]), "r"(b[0]), "r"(b[1]));
}
__device__ __forceinline__ void cpasync16(void* smem_dst, const void* gptr) {
    uint32_t d = (uint32_t)__cvta_generic_to_shared(smem_dst);
    asm volatile("cp.async.ca.shared.global [%0], [%1], 16;\n" :: "r"(d), "l"(gptr));
}

// ---------------- prep kernels ----------------------------------------------
__global__ void mask_kernel(const int* __restrict__ mask,
                            const int* __restrict__ ncount) {
    int idx = blockIdx.x * 256 + threadIdx.x;
    if (idx < M_) {
        int b = idx >> 9;
        int n = idx & 511;
        bool inv = (mask[2*idx] != 0) || (mask[2*idx+1] != 0) || (n >= ncount[b]);
        g_inv[idx] = inv ? 1 : 0;
    }
}

__global__ void round_w_kernel(const float* __restrict__ Wq, const float* __restrict__ Wk,
                               const float* __restrict__ Wv, const float* __restrict__ Wo) {
    int idx = blockIdx.x * 256 + threadIdx.x;     // 65536 float4 slots total
    int m = idx >> 14;                            // matrix 0..3
    int off = (idx & 16383) * 4;
    const float* src = (m == 0) ? Wq : (m == 1) ? Wk : (m == 2) ? Wv : Wo;
    float4 v = *(const float4*)&src[off];
    *(float4*)&g_wr[m*D_*D_ + off] = tf32x4(v);
}

// ---------------- tf32 mma GEMM: C[Mx256] = A[Mx256] @ W[256x256] (+bias,+res)
// block 128x128, BK=32, 128 threads, 4 warps of 64x64; cp.async 3-stage ring
#define GSTAGE_FLTS 8960          // As 128*36 + Bs 32*136
#define GEMM_SMEM_BYTES (3*GSTAGE_FLTS*4)

template<bool RES, bool ROUND>
__device__ __forceinline__ void gemm_body(const float* __restrict__ A,
                                          const float* __restrict__ W,
                                          const float* __restrict__ bias,
                                          const float* __restrict__ res,
                                          float* __restrict__ C) {
    extern __shared__ float smem[];

    const int tid  = threadIdx.x;
    const int lane = tid & 31, warp = tid >> 5;
    const int g = lane >> 2, t = lane & 3;
    const int mw = (warp >> 1) * 64, nw = (warp & 1) * 64;
    const int row0 = blockIdx.x * 128, col0 = blockIdx.y * 128;

    const int ar = tid >> 3, ac = (tid & 7) * 4;     // A loader (128x32)
    const int br = tid >> 5, bc = (tid & 31) * 4;    // B loader (32x128)

    float acc[4][8][4];
#pragma unroll
    for (int i = 0; i < 4; i++)
#pragma unroll
        for (int j = 0; j < 8; j++)
#pragma unroll
            for (int q = 0; q < 4; q++) acc[i][j][q] = 0.f;

    const float* gA = &A[(size_t)(row0 + ar)*D_ + ac];
    const float* gB = &W[(size_t)br*D_ + col0 + bc];

    auto issue = [&](int chunk, int stage) {
        float* As = smem + stage * GSTAGE_FLTS;
        float* Bs = As + 4608;
#pragma unroll
        for (int p = 0; p < 8; p++)
            cpasync16(&As[(ar + 16*p)*36 + ac], gA + (size_t)16*p*D_ + chunk*32);
#pragma unroll
        for (int p = 0; p < 8; p++)
            cpasync16(&Bs[(br + 4*p)*136 + bc], gB + (size_t)(chunk*32 + 4*p)*D_);
        asm volatile("cp.async.commit_group;\n" ::: "memory");
    };

    issue(0, 0);
    issue(1, 1);

    for (int i = 0; i < 8; i++) {
        if (i < 7) asm volatile("cp.async.wait_group 1;\n" ::: "memory");
        else       asm volatile("cp.async.wait_group 0;\n" ::: "memory");
        __syncthreads();
        if (i < 6) issue(i + 2, (i + 2) % 3);

        const float* As = smem + (i % 3) * GSTAGE_FLTS;
        const float* Bs = As + 4608;
#pragma unroll
        for (int ks = 0; ks < 4; ks++) {
            const int k = ks * 8;
            uint32_t af[4][4];
#pragma unroll
            for (int ma = 0; ma < 4; ma++) {
                const float* ab = &As[(mw + ma*16 + g)*36 + k + t];
                af[ma][0] = __float_as_uint(ab[0]);
                af[ma][1] = __float_as_uint(ab[8*36]);
                af[ma][2] = __float_as_uint(ab[4]);
                af[ma][3] = __float_as_uint(ab[8*36 + 4]);
            }
#pragma unroll
            for (int na = 0; na < 8; na++) {
                const float* bb = &Bs[(k + t)*136 + nw + na*8 + g];
                uint32_t bf[2] = {__float_as_uint(bb[0]), __float_as_uint(bb[4*136])};
#pragma unroll
                for (int ma = 0; ma < 4; ma++) mma_tf32(acc[ma][na], af[ma], bf);
            }
        }
        __syncthreads();
    }

#pragma unroll
    for (int ma = 0; ma < 4; ma++) {
        const int r0g = row0 + mw + ma*16 + g;
#pragma unroll
        for (int na = 0; na < 8; na++) {
            const int c0 = col0 + nw + na*8 + 2*t;
            float2 o0, o1;
            o0.x = acc[ma][na][0] + bias[c0];
            o0.y = acc[ma][na][1] + bias[c0+1];
            o1.x = acc[ma][na][2] + bias[c0];
            o1.y = acc[ma][na][3] + bias[c0+1];
            if (RES) {
                float2 ra = *(const float2*)&res[(size_t)r0g*D_ + c0];
                float2 rb = *(const float2*)&res[(size_t)(r0g+8)*D_ + c0];
                o0.x += ra.x; o0.y += ra.y;
                o1.x += rb.x; o1.y += rb.y;
            }
            if (ROUND) {
                o0.x = to_tf32(o0.x); o0.y = to_tf32(o0.y);
                o1.x = to_tf32(o1.x); o1.y = to_tf32(o1.y);
            }
            *(float2*)&C[(size_t)r0g*D_ + c0]     = o0;
            *(float2*)&C[(size_t)(r0g+8)*D_ + c0] = o1;
        }
    }
}

__global__ void __launch_bounds__(128, 2)
qkv_kernel(const float* __restrict__ A,
           const float* __restrict__ bq, const float* __restrict__ bk,
           const float* __restrict__ bv) {
    const int z = blockIdx.z;
    const float* W  = g_wr + z*D_*D_;
    const float* bb = (z == 0) ? bq : (z == 1) ? bk : bv;
    float* C        = (z == 0) ? g_q : (z == 1) ? g_k : g_v;
    gemm_body<false, true>(A, W, bb, nullptr, C);
}

__global__ void __launch_bounds__(128, 2)
oproj_kernel(const float* __restrict__ bo,
             const float* __restrict__ hres, float* __restrict__ out) {
    gemm_body<true, false>(g_ao, g_wr + 3*D_*D_, bo, hres, out);
}

// ---------------- fused attention (tf32 mma, 512 threads, K/V smem-resident)
// smem floats: Qs[32][36] | Ks[512][36] | Vs[512][40] | Ss[32][524] | rsum[32] | inv[512]B
#define OFF_Q  0
#define OFF_K  1152
#define OFF_V  19584
#define OFF_S  40064
#define OFF_RS 56832
#define ATTN_SMEM_BYTES (56864*4 + 512)   // 227,968 B

__global__ void __launch_bounds__(512, 1)
attn_kernel() {
    extern __shared__ float sm[];
    float* Qs   = sm + OFF_Q;
    float* Ks   = sm + OFF_K;
    float* Vs   = sm + OFF_V;
    float* Ss   = sm + OFF_S;
    float* rsum = sm + OFF_RS;
    unsigned char* sinv = (unsigned char*)(sm + 56864);

    const int tid  = threadIdx.x;
    const int lane = tid & 31, warp = tid >> 5;     // warp 0..15
    const int g = lane >> 2, t = lane & 3;
    const int bh   = blockIdx.x >> 1;
    const int half = blockIdx.x & 1;
    const int b  = bh >> 3;
    const int hh = bh & 7;

    const float* Qg = g_q  + (size_t)b*N_*D_ + hh*DK_;
    const float* Kg = g_k  + (size_t)b*N_*D_ + hh*DK_;
    const float* Vg = g_v  + (size_t)b*N_*D_ + hh*DK_;
    float*       Og = g_ao + (size_t)b*N_*D_ + hh*DK_;

    sinv[tid] = g_inv[b*N_ + tid];

    // ---- load K and V fully into smem (pre-rounded data: plain copy) ----
    {
        const int r = tid >> 3, c = (tid & 7) * 4;
#pragma unroll
        for (int p = 0; p < 8; p++) {
            const int key = r + 64*p;
            *(float4*)&Ks[key*36 + c] = *(const float4*)&Kg[(size_t)key*D_ + c];
            *(float4*)&Vs[key*40 + c] = *(const float4*)&Vg[(size_t)key*D_ + c];
        }
    }
    __syncthreads();

    const float rscale = 0.17677669529663689f;  // 1/sqrt(32)

    for (int qt = 0; qt < 8; qt++) {
        const int q0 = half*256 + qt*32;

        // ---- load Q tile 32x32 ----
        {
            const int r = tid >> 4, c = (tid & 15) * 2;
            *(float2*)&Qs[r*36 + c] = *(const float2*)&Qg[(size_t)(q0 + r)*D_ + c];
        }
        __syncthreads();

        // ---- phase 1: S = Q @ K^T ; warp w covers keys [32w, 32w+32) ----
        {
            const int nwk = warp * 32;
            float acc[2][4][4];
#pragma unroll
            for (int i = 0; i < 2; i++)
#pragma unroll
                for (int j = 0; j < 4; j++)
#pragma unroll
                    for (int q = 0; q < 4; q++) acc[i][j][q] = 0.f;

#pragma unroll
            for (int ks = 0; ks < 4; ks++) {
                const int k = ks * 8;
                uint32_t af[2][4];
#pragma unroll
                for (int ma = 0; ma < 2; ma++) {
                    const float* ab = &Qs[(ma*16 + g)*36 + k + t];
                    af[ma][0] = __float_as_uint(ab[0]);
                    af[ma][1] = __float_as_uint(ab[8*36]);
                    af[ma][2] = __float_as_uint(ab[4]);
                    af[ma][3] = __float_as_uint(ab[8*36 + 4]);
                }
#pragma unroll
                for (int na = 0; na < 4; na++) {
                    const float* bb = &Ks[(nwk + na*8 + g)*36 + k + t];
                    uint32_t bf[2] = {__float_as_uint(bb[0]), __float_as_uint(bb[4])};
                    mma_tf32(acc[0][na], af[0], bf);
                    mma_tf32(acc[1][na], af[1], bf);
                }
            }
#pragma unroll
            for (int ma = 0; ma < 2; ma++) {
                const int r0 = ma*16 + g;
                const bool iqa = sinv[q0 + r0] != 0;
                const bool iqb = sinv[q0 + r0 + 8] != 0;
#pragma unroll
                for (int na = 0; na < 4; na++) {
                    const int col = nwk + na*8 + 2*t;
                    const bool ik0 = sinv[col] != 0;
                    const bool ik1 = sinv[col + 1] != 0;
                    float2 s0, s1;
                    s0.x = (iqa || ik0) ? -1e9f : acc[ma][na][0] * rscale;
                    s0.y = (iqa || ik1) ? -1e9f : acc[ma][na][1] * rscale;
                    s1.x = (iqb || ik0) ? -1e9f : acc[ma][na][2] * rscale;
                    s1.y = (iqb || ik1) ? -1e9f : acc[ma][na][3] * rscale;
                    *(float2*)&Ss[r0*524 + col]     = s0;
                    *(float2*)&Ss[(r0+8)*524 + col] = s1;
                }
            }
        }
        __syncthreads();

        // ---- phase 2: softmax, 16 threads per row ----
        {
            const int r  = tid >> 4;
            const int sg = tid & 15;
            float* srow = &Ss[r*524 + sg*4];
            float m = -1e30f;
#pragma unroll
            for (int i = 0; i < 8; i++) {
                float4 v = *(float4*)&srow[i*64];
                m = fmaxf(m, fmaxf(fmaxf(v.x, v.y), fmaxf(v.z, v.w)));
            }
            m = fmaxf(m, __shfl_xor_sync(0xffffffffu, m, 1));
            m = fmaxf(m, __shfl_xor_sync(0xffffffffu, m, 2));
            m = fmaxf(m, __shfl_xor_sync(0xffffffffu, m, 4));
            m = fmaxf(m, __shfl_xor_sync(0xffffffffu, m, 8));
            float s = 0.f;
#pragma unroll
            for (int i = 0; i < 8; i++) {
                float4 v = *(float4*)&srow[i*64];
                v.x = __expf(v.x - m); v.y = __expf(v.y - m);
                v.z = __expf(v.z - m); v.w = __expf(v.w - m);
                *(float4*)&srow[i*64] = v;
                s += v.x + v.y + v.z + v.w;
            }
            s += __shfl_xor_sync(0xffffffffu, s, 1);
            s += __shfl_xor_sync(0xffffffffu, s, 2);
            s += __shfl_xor_sync(0xffffffffu, s, 4);
            s += __shfl_xor_sync(0xffffffffu, s, 8);
            if (sg == 0) rsum[r] = s;
        }
        __syncthreads();

        // ---- phase 3: O = P @ V ; warp (kw=w>>1, nh=w&1) ----
        {
            const int kw = (warp >> 1) * 64;
            const int nh = (warp & 1) * 16;
            float acc3[2][2][4];
#pragma unroll
            for (int i = 0; i < 2; i++)
#pragma unroll
                for (int j = 0; j < 2; j++)
#pragma unroll
                    for (int q = 0; q < 4; q++) acc3[i][j][q] = 0.f;

#pragma unroll
            for (int ks = 0; ks < 8; ks++) {
                const int k = kw + ks*8;
                uint32_t af[2][4];
#pragma unroll
                for (int ma = 0; ma < 2; ma++) {
                    const float* ab = &Ss[(ma*16 + g)*524 + k + t];
                    af[ma][0] = __float_as_uint(ab[0]);
                    af[ma][1] = __float_as_uint(ab[8*524]);
                    af[ma][2] = __float_as_uint(ab[4]);
                    af[ma][3] = __float_as_uint(ab[8*524 + 4]);
                }
#pragma unroll
                for (int na = 0; na < 2; na++) {
                    const float* bb = &Vs[(k + t)*40 + nh + na*8 + g];
                    uint32_t bf[2] = {__float_as_uint(bb[0]), __float_as_uint(bb[4*40])};
                    mma_tf32(acc3[0][na], af[0], bf);
                    mma_tf32(acc3[1][na], af[1], bf);
                }
            }
            __syncthreads();   // all warps done reading P
            // write partials: part[kw8][32][40] into Ss region
            float* op = Ss + (warp >> 1) * 1280;
#pragma unroll
            for (int ma = 0; ma < 2; ma++) {
                const int r0 = ma*16 + g;
#pragma unroll
                for (int na = 0; na < 2; na++) {
                    const int col = nh + na*8 + 2*t;
                    *(float2*)&op[r0*40 + col]     = make_float2(acc3[ma][na][0], acc3[ma][na][1]);
                    *(float2*)&op[(r0+8)*40 + col] = make_float2(acc3[ma][na][2], acc3[ma][na][3]);
                }
            }
        }
        __syncthreads();

        // ---- reduce 8 partials, normalize, store (rounded) ----
        {
            const int q  = tid >> 4;
            const int c2 = (tid & 15) * 2;
            float2 o = {0.f, 0.f};
#pragma unroll
            for (int w = 0; w < 8; w++) {
                float2 p = *(float2*)&Ss[w*1280 + q*40 + c2];
                o.x += p.x; o.y += p.y;
            }
            const float rs = 1.0f / rsum[q];
            *(float2*)&Og[(size_t)(q0 + q)*D_ + c2] =
                make_float2(to_tf32(o.x * rs), to_tf32(o.y * rs));
        }
        __syncthreads();
    }
}

// ---------------- launcher --------------------------------------------------
extern "C" void kernel_launch(void* const* d_in, const int* in_sizes, int n_in,
                              void* d_out, int out_size) {
    const float* h    = (const float*)d_in[0];
    const int*   mask = (const int*)  d_in[1];
    const int*   nc   = (const int*)  d_in[2];
    const float* Wq   = (const float*)d_in[3];
    const float* bq   = (const float*)d_in[4];
    const float* Wk   = (const float*)d_in[5];
    const float* bk   = (const float*)d_in[6];
    const float* Wv   = (const float*)d_in[7];
    const float* bv   = (const float*)d_in[8];
    const float* Wo   = (const float*)d_in[9];
    const float* bo   = (const float*)d_in[10];
    float* out = (float*)d_out;

    cudaFuncSetAttribute(attn_kernel, cudaFuncAttributeMaxDynamicSharedMemorySize,
                         ATTN_SMEM_BYTES);
    cudaFuncSetAttribute(qkv_kernel, cudaFuncAttributeMaxDynamicSharedMemorySize,
                         GEMM_SMEM_BYTES);
    cudaFuncSetAttribute(oproj_kernel, cudaFuncAttributeMaxDynamicSharedMemorySize,
                         GEMM_SMEM_BYTES);

    mask_kernel<<<M_/256, 256>>>(mask, nc);
    round_w_kernel<<<256, 256>>>(Wq, Wk, Wv, Wo);
    qkv_kernel<<<dim3(M_/128, D_/128, 3), 128, GEMM_SMEM_BYTES>>>(h, bq, bk, bv);
    attn_kernel<<<B_*H_*2, 512, ATTN_SMEM_BYTES>>>();
    oproj_kernel<<<dim3(M_/128, D_/128), 128, GEMM_SMEM_BYTES>>>(bo, h, out);
}

// round 6
// speedup vs baseline: 2.9635x; 1.0657x over previous
#include <cuda_runtime.h>
#include <math.h>
#include <stdint.h>

#define B_  64
#define N_  512
#define D_  256
#define H_  8
#define DK_ 32
#define M_  (B_*N_)   // 32768

// ---------------- scratch (static device globals; no allocation) ----------
__device__ __align__(256) float g_q[M_*D_];
__device__ __align__(256) float g_k[M_*D_];
__device__ __align__(256) float g_v[M_*D_];
__device__ __align__(256) float g_ao[M_*D_];
__device__ __align__(256) float g_wr[4*D_*D_];   // tf32-rounded Wq,Wk,Wv,Wo
__device__ unsigned char g_inv[M_];
__device__ unsigned int  g_invbits[M_/32];

// ---------------- helpers ---------------------------------------------------
__device__ __forceinline__ float to_tf32(float x) {
    uint32_t r;
    asm("cvt.rna.tf32.f32 %0, %1;" : "=r"(r) : "f"(x));
    return __uint_as_float(r);
}
__device__ __forceinline__ float4 tf32x4(float4 v) {
    return make_float4(to_tf32(v.x), to_tf32(v.y), to_tf32(v.z), to_tf32(v.w));
}
__device__ __forceinline__ void mma_tf32(float* d, const uint32_t* a, const uint32_t* b) {
    asm volatile(
        "mma.sync.aligned.m16n8k8.row.col.f32.tf32.tf32.f32 "
        "{%0,%1,%2,%3}, {%4,%5,%6,%7}, {%8,%9}, {%0,%1,%2,%3};\n"
        : "+f"(d[0]), "+f"(d[1]), "+f"(d[2]), "+f"(d[3])
        : "r"(a[0]), "r"(a[1]), "r"(a[2]), "r"(a[3]), "r"(b[0]), "r"(b[1]));
}
__device__ __forceinline__ void cpasync16(void* smem_dst, const void* gptr) {
    uint32_t d = (uint32_t)__cvta_generic_to_shared(smem_dst);
    asm volatile("cp.async.ca.shared.global [%0], [%1], 16;\n" :: "r"(d), "l"(gptr));
}

// ---------------- prep kernels ----------------------------------------------
__global__ void mask_kernel(const int* __restrict__ mask,
                            const int* __restrict__ ncount) {
    int idx = blockIdx.x * 256 + threadIdx.x;
    if (idx < M_) {
        int b = idx >> 9;
        int n = idx & 511;
        bool inv = (mask[2*idx] != 0) || (mask[2*idx+1] != 0) || (n >= ncount[b]);
        g_inv[idx] = inv ? 1 : 0;
        unsigned bal = __ballot_sync(0xffffffffu, inv);
        if ((threadIdx.x & 31) == 0) g_invbits[idx >> 5] = bal;
    }
}

__global__ void round_w_kernel(const float* __restrict__ Wq, const float* __restrict__ Wk,
                               const float* __restrict__ Wv, const float* __restrict__ Wo) {
    int idx = blockIdx.x * 256 + threadIdx.x;     // 65536 float4 slots total
    int m = idx >> 14;                            // matrix 0..3
    int off = (idx & 16383) * 4;
    const float* src = (m == 0) ? Wq : (m == 1) ? Wk : (m == 2) ? Wv : Wo;
    float4 v = *(const float4*)&src[off];
    *(float4*)&g_wr[m*D_*D_ + off] = tf32x4(v);
}

// ---------------- tf32 mma GEMM (validated in R3) ----------------------------
#define GSTAGE_FLTS 8960          // As 128*36 + Bs 32*136
#define GEMM_SMEM_BYTES (3*GSTAGE_FLTS*4)

template<bool RES, bool ROUND>
__device__ __forceinline__ void gemm_body(const float* __restrict__ A,
                                          const float* __restrict__ W,
                                          const float* __restrict__ bias,
                                          const float* __restrict__ res,
                                          float* __restrict__ C) {
    extern __shared__ float smem[];

    const int tid  = threadIdx.x;
    const int lane = tid & 31, warp = tid >> 5;
    const int g = lane >> 2, t = lane & 3;
    const int mw = (warp >> 1) * 64, nw = (warp & 1) * 64;
    const int row0 = blockIdx.x * 128, col0 = blockIdx.y * 128;

    const int ar = tid >> 3, ac = (tid & 7) * 4;
    const int br = tid >> 5, bc = (tid & 31) * 4;

    float acc[4][8][4];
#pragma unroll
    for (int i = 0; i < 4; i++)
#pragma unroll
        for (int j = 0; j < 8; j++)
#pragma unroll
            for (int q = 0; q < 4; q++) acc[i][j][q] = 0.f;

    const float* gA = &A[(size_t)(row0 + ar)*D_ + ac];
    const float* gB = &W[(size_t)br*D_ + col0 + bc];

    auto issue = [&](int chunk, int stage) {
        float* As = smem + stage * GSTAGE_FLTS;
        float* Bs = As + 4608;
#pragma unroll
        for (int p = 0; p < 8; p++)
            cpasync16(&As[(ar + 16*p)*36 + ac], gA + (size_t)16*p*D_ + chunk*32);
#pragma unroll
        for (int p = 0; p < 8; p++)
            cpasync16(&Bs[(br + 4*p)*136 + bc], gB + (size_t)(chunk*32 + 4*p)*D_);
        asm volatile("cp.async.commit_group;\n" ::: "memory");
    };

    issue(0, 0);
    issue(1, 1);

    for (int i = 0; i < 8; i++) {
        if (i < 7) asm volatile("cp.async.wait_group 1;\n" ::: "memory");
        else       asm volatile("cp.async.wait_group 0;\n" ::: "memory");
        __syncthreads();
        if (i < 6) issue(i + 2, (i + 2) % 3);

        const float* As = smem + (i % 3) * GSTAGE_FLTS;
        const float* Bs = As + 4608;
#pragma unroll
        for (int ks = 0; ks < 4; ks++) {
            const int k = ks * 8;
            uint32_t af[4][4];
#pragma unroll
            for (int ma = 0; ma < 4; ma++) {
                const float* ab = &As[(mw + ma*16 + g)*36 + k + t];
                af[ma][0] = __float_as_uint(ab[0]);
                af[ma][1] = __float_as_uint(ab[8*36]);
                af[ma][2] = __float_as_uint(ab[4]);
                af[ma][3] = __float_as_uint(ab[8*36 + 4]);
            }
#pragma unroll
            for (int na = 0; na < 8; na++) {
                const float* bb = &Bs[(k + t)*136 + nw + na*8 + g];
                uint32_t bf[2] = {__float_as_uint(bb[0]), __float_as_uint(bb[4*136])};
#pragma unroll
                for (int ma = 0; ma < 4; ma++) mma_tf32(acc[ma][na], af[ma], bf);
            }
        }
        __syncthreads();
    }

#pragma unroll
    for (int ma = 0; ma < 4; ma++) {
        const int r0g = row0 + mw + ma*16 + g;
#pragma unroll
        for (int na = 0; na < 8; na++) {
            const int c0 = col0 + nw + na*8 + 2*t;
            float2 o0, o1;
            o0.x = acc[ma][na][0] + bias[c0];
            o0.y = acc[ma][na][1] + bias[c0+1];
            o1.x = acc[ma][na][2] + bias[c0];
            o1.y = acc[ma][na][3] + bias[c0+1];
            if (RES) {
                float2 ra = *(const float2*)&res[(size_t)r0g*D_ + c0];
                float2 rb = *(const float2*)&res[(size_t)(r0g+8)*D_ + c0];
                o0.x += ra.x; o0.y += ra.y;
                o1.x += rb.x; o1.y += rb.y;
            }
            if (ROUND) {
                o0.x = to_tf32(o0.x); o0.y = to_tf32(o0.y);
                o1.x = to_tf32(o1.x); o1.y = to_tf32(o1.y);
            }
            *(float2*)&C[(size_t)r0g*D_ + c0]     = o0;
            *(float2*)&C[(size_t)(r0g+8)*D_ + c0] = o1;
        }
    }
}

__global__ void __launch_bounds__(128)
qkv_kernel(const float* __restrict__ A,
           const float* __restrict__ bq, const float* __restrict__ bk,
           const float* __restrict__ bv) {
    const int z = blockIdx.z;
    const float* W  = g_wr + z*D_*D_;
    const float* bb = (z == 0) ? bq : (z == 1) ? bk : bv;
    float* C        = (z == 0) ? g_q : (z == 1) ? g_k : g_v;
    gemm_body<false, true>(A, W, bb, nullptr, C);
}

__global__ void __launch_bounds__(128)
oproj_kernel(const float* __restrict__ bo,
             const float* __restrict__ hres, float* __restrict__ out) {
    gemm_body<true, false>(g_ao, g_wr + 3*D_*D_, bo, hres, out);
}

// ---------------- register-flash attention ----------------------------------
// 512 thr / 16 warps; warp = (ma 0..3) x (kspl 0..3): 16 q-rows x 128 keys.
// S in regs; mask/max/exp/sum in regs; P fed to P@V mma via quad shuffles.
#define OFF_K   0                 // Ks[512][36]
#define OFF_V   18432             // Vs[512][40]
#define OFF_QS  38912             // Qs[64][36]
#define OFF_OP  41216             // Opart[16 warps][16][40]
#define OFF_MR  51456             // Mred[64][4]
#define OFF_SR  51712             // Sred[64][4]
#define ATTN_SMEM_FLTS 51968
#define ATTN_SMEM_BYTES (ATTN_SMEM_FLTS*4)   // 207,872 B

__global__ void __launch_bounds__(512)
attn_kernel() {
    extern __shared__ float sm[];
    float* Ks   = sm + OFF_K;
    float* Vs   = sm + OFF_V;
    float* Qs   = sm + OFF_QS;
    float* Op   = sm + OFF_OP;
    float* Mred = sm + OFF_MR;
    float* Sred = sm + OFF_SR;

    const int tid  = threadIdx.x;
    const int lane = tid & 31, warp = tid >> 5;
    const int g = lane >> 2, t = lane & 3;
    const int ma   = warp >> 2;          // q-row atom 0..3
    const int kspl = warp & 3;           // key-split 0..3
    const int bh   = blockIdx.x >> 1;
    const int half = blockIdx.x & 1;
    const int b  = bh >> 3;
    const int hh = bh & 7;

    const float* Qg = g_q  + (size_t)b*N_*D_ + hh*DK_;
    const float* Kg = g_k  + (size_t)b*N_*D_ + hh*DK_;
    const float* Vg = g_v  + (size_t)b*N_*D_ + hh*DK_;
    float*       Og = g_ao + (size_t)b*N_*D_ + hh*DK_;

    // key-invalid bitmask for this warp's 128 keys; pre-shift per thread
    uint32_t invw[4];
#pragma unroll
    for (int j = 0; j < 4; j++)
        invw[j] = g_invbits[b*16 + kspl*4 + j] >> (t << 1);

    // ---- load K and V fully into smem (pre-rounded data: plain copy) ----
    {
        const int r = tid >> 3, c = (tid & 7) * 4;
#pragma unroll
        for (int p = 0; p < 8; p++) {
            const int key = r + 64*p;
            *(float4*)&Ks[key*36 + c] = *(const float4*)&Kg[(size_t)key*D_ + c];
            *(float4*)&Vs[key*40 + c] = *(const float4*)&Vg[(size_t)key*D_ + c];
        }
    }

    const float rscale = 0.17677669529663689f;  // 1/sqrt(32)
    const int kb0 = kspl * 128;
    const int rr0 = ma*16 + g;                   // row within 64-row tile
    const int s1 = (lane & 28) + (t >> 1);       // quad shuffle sources
    const int s2 = s1 + 2;
    const bool par = (t & 1) != 0;
    const uint32_t FULL = 0xffffffffu;

    for (int qt = 0; qt < 4; qt++) {
        const int q0 = half*256 + qt*64;

        // ---- stage Q tile 64x32 ----
        __syncthreads();     // Opart/Qs free (also covers initial K/V load at qt=0)
        {
            const int r = tid >> 3, c = (tid & 7) * 4;
            *(float4*)&Qs[r*36 + c] = *(const float4*)&Qg[(size_t)(q0 + r)*D_ + c];
        }
        __syncthreads();

        // query-invalid flags for this thread's two rows
        const bool iq0 = g_inv[b*N_ + q0 + rr0]     != 0;
        const bool iq1 = g_inv[b*N_ + q0 + rr0 + 8] != 0;

        // ---- phase A: S[16 x 128] = Q @ K^T in registers ----
        uint32_t af[4][4];
#pragma unroll
        for (int ko = 0; ko < 4; ko++) {
            const float* ab = &Qs[rr0*36 + ko*8 + t];
            af[ko][0] = __float_as_uint(ab[0]);
            af[ko][1] = __float_as_uint(ab[8*36]);
            af[ko][2] = __float_as_uint(ab[4]);
            af[ko][3] = __float_as_uint(ab[8*36 + 4]);
        }

        float acc[16][4];
#pragma unroll
        for (int na = 0; na < 16; na++) {
            acc[na][0] = acc[na][1] = acc[na][2] = acc[na][3] = 0.f;
#pragma unroll
            for (int ko = 0; ko < 4; ko++) {
                const float* bb = &Ks[(kb0 + na*8 + g)*36 + ko*8 + t];
                uint32_t bf[2] = {__float_as_uint(bb[0]), __float_as_uint(bb[4])};
                mma_tf32(acc[na], af[ko], bf);
            }
        }

        // ---- mask + scale (regs), per-warp row max ----
        float mx0 = -1e30f, mx1 = -1e30f;
#pragma unroll
        for (int na = 0; na < 16; na++) {
            const uint32_t w = invw[na >> 2] >> ((na & 3) << 3);
            const bool ik0 = (w & 1u) != 0;
            const bool ik1 = (w & 2u) != 0;
            acc[na][0] = (iq0 || ik0) ? -1e9f : acc[na][0] * rscale;
            acc[na][1] = (iq0 || ik1) ? -1e9f : acc[na][1] * rscale;
            acc[na][2] = (iq1 || ik0) ? -1e9f : acc[na][2] * rscale;
            acc[na][3] = (iq1 || ik1) ? -1e9f : acc[na][3] * rscale;
            mx0 = fmaxf(mx0, fmaxf(acc[na][0], acc[na][1]));
            mx1 = fmaxf(mx1, fmaxf(acc[na][2], acc[na][3]));
        }
        mx0 = fmaxf(mx0, __shfl_xor_sync(FULL, mx0, 1));
        mx0 = fmaxf(mx0, __shfl_xor_sync(FULL, mx0, 2));
        mx1 = fmaxf(mx1, __shfl_xor_sync(FULL, mx1, 1));
        mx1 = fmaxf(mx1, __shfl_xor_sync(FULL, mx1, 2));
        if (t == 0) {
            Mred[rr0*4 + kspl]     = mx0;
            Mred[(rr0+8)*4 + kspl] = mx1;
        }
        __syncthreads();

        // global row max
        float4 m4a = *(float4*)&Mred[rr0*4];
        float4 m4b = *(float4*)&Mred[(rr0+8)*4];
        const float M0 = fmaxf(fmaxf(m4a.x, m4a.y), fmaxf(m4a.z, m4a.w));
        const float M1 = fmaxf(fmaxf(m4b.x, m4b.y), fmaxf(m4b.z, m4b.w));

        // ---- exp + row sum (regs), round P to tf32 ----
        float sm0 = 0.f, sm1 = 0.f;
#pragma unroll
        for (int na = 0; na < 16; na++) {
            float e0 = __expf(acc[na][0] - M0);
            float e1 = __expf(acc[na][1] - M0);
            float e2 = __expf(acc[na][2] - M1);
            float e3 = __expf(acc[na][3] - M1);
            sm0 += e0 + e1;
            sm1 += e2 + e3;
            acc[na][0] = to_tf32(e0);
            acc[na][1] = to_tf32(e1);
            acc[na][2] = to_tf32(e2);
            acc[na][3] = to_tf32(e3);
        }
        sm0 += __shfl_xor_sync(FULL, sm0, 1);
        sm0 += __shfl_xor_sync(FULL, sm0, 2);
        sm1 += __shfl_xor_sync(FULL, sm1, 1);
        sm1 += __shfl_xor_sync(FULL, sm1, 2);
        if (t == 0) {
            Sred[rr0*4 + kspl]     = sm0;
            Sred[(rr0+8)*4 + kspl] = sm1;
        }

        // ---- phase 3: O_partial[16 x 32] = P @ V(128-key slice) ----
        float oacc[4][4];
#pragma unroll
        for (int na = 0; na < 4; na++)
#pragma unroll
            for (int q = 0; q < 4; q++) oacc[na][q] = 0.f;

#pragma unroll
        for (int ko = 0; ko < 16; ko++) {
            // A-frag of P for k-octet ko via quad shuffles
            float v00 = __shfl_sync(FULL, acc[ko][0], s1);
            float v01 = __shfl_sync(FULL, acc[ko][1], s1);
            float v20 = __shfl_sync(FULL, acc[ko][2], s1);
            float v21 = __shfl_sync(FULL, acc[ko][3], s1);
            float w00 = __shfl_sync(FULL, acc[ko][0], s2);
            float w01 = __shfl_sync(FULL, acc[ko][1], s2);
            float w20 = __shfl_sync(FULL, acc[ko][2], s2);
            float w21 = __shfl_sync(FULL, acc[ko][3], s2);
            uint32_t pf[4];
            pf[0] = __float_as_uint(par ? v01 : v00);
            pf[1] = __float_as_uint(par ? v21 : v20);
            pf[2] = __float_as_uint(par ? w01 : w00);
            pf[3] = __float_as_uint(par ? w21 : w20);

            const int kk = kb0 + ko*8;
#pragma unroll
            for (int na = 0; na < 4; na++) {
                const float* bb = &Vs[(kk + t)*40 + na*8 + g];
                uint32_t bf[2] = {__float_as_uint(bb[0]), __float_as_uint(bb[4*40])};
                mma_tf32(oacc[na], pf, bf);
            }
        }

        // ---- store partials ----
        {
            float* op = Op + warp * 640;
#pragma unroll
            for (int na = 0; na < 4; na++) {
                const int c = na*8 + 2*t;
                *(float2*)&op[g*40 + c]     = make_float2(oacc[na][0], oacc[na][1]);
                *(float2*)&op[(g+8)*40 + c] = make_float2(oacc[na][2], oacc[na][3]);
            }
        }
        __syncthreads();

        // ---- combine 4 key-split partials, normalize, store ----
        {
            const int r  = tid >> 3;            // 0..63
            const int c4 = (tid & 7) * 4;       // 0..28
            const int wb = (r >> 4) * 4;        // ma*4
            const int rl = r & 15;
            float4 o = {0.f, 0.f, 0.f, 0.f};
#pragma unroll
            for (int kk = 0; kk < 4; kk++) {
                float4 p = *(float4*)&Op[(wb + kk)*640 + rl*40 + c4];
                o.x += p.x; o.y += p.y; o.z += p.z; o.w += p.w;
            }
            float4 s4 = *(float4*)&Sred[r*4];
            const float rs = 1.0f / (s4.x + s4.y + s4.z + s4.w);
            float4 ov = make_float4(to_tf32(o.x*rs), to_tf32(o.y*rs),
                                    to_tf32(o.z*rs), to_tf32(o.w*rs));
            *(float4*)&Og[(size_t)(q0 + r)*D_ + c4] = ov;
        }
    }
}

// ---------------- launcher --------------------------------------------------
extern "C" void kernel_launch(void* const* d_in, const int* in_sizes, int n_in,
                              void* d_out, int out_size) {
    const float* h    = (const float*)d_in[0];
    const int*   mask = (const int*)  d_in[1];
    const int*   nc   = (const int*)  d_in[2];
    const float* Wq   = (const float*)d_in[3];
    const float* bq   = (const float*)d_in[4];
    const float* Wk   = (const float*)d_in[5];
    const float* bk   = (const float*)d_in[6];
    const float* Wv   = (const float*)d_in[7];
    const float* bv   = (const float*)d_in[8];
    const float* Wo   = (const float*)d_in[9];
    const float* bo   = (const float*)d_in[10];
    float* out = (float*)d_out;

    cudaFuncSetAttribute(attn_kernel, cudaFuncAttributeMaxDynamicSharedMemorySize,
                         ATTN_SMEM_BYTES);
    cudaFuncSetAttribute(qkv_kernel, cudaFuncAttributeMaxDynamicSharedMemorySize,
                         GEMM_SMEM_BYTES);
    cudaFuncSetAttribute(oproj_kernel, cudaFuncAttributeMaxDynamicSharedMemorySize,
                         GEMM_SMEM_BYTES);

    mask_kernel<<<M_/256, 256>>>(mask, nc);
    round_w_kernel<<<256, 256>>>(Wq, Wk, Wv, Wo);
    qkv_kernel<<<dim3(M_/128, D_/128, 3), 128, GEMM_SMEM_BYTES>>>(h, bq, bk, bv);
    attn_kernel<<<B_*H_*2, 512, ATTN_SMEM_BYTES>>>();
    oproj_kernel<<<dim3(M_/128, D_/128), 128, GEMM_SMEM_BYTES>>>(bo, h, out);
}

// round 7
// speedup vs baseline: 3.4602x; 1.1676x over previous
#include <cuda_runtime.h>
#include <cuda_fp16.h>
#include <math.h>
#include <stdint.h>

#define B_  64
#define N_  512
#define D_  256
#define H_  8
#define DK_ 32
#define M_  (B_*N_)   // 32768

// ---------------- scratch (static device globals; no allocation) ----------
__device__ __align__(256) float g_q[M_*D_];
__device__ __align__(256) float g_k[M_*D_];
__device__ __align__(256) float g_v[M_*D_];
__device__ __align__(256) float g_ao[M_*D_];
__device__ __align__(256) float g_wr[4*D_*D_];   // tf32-rounded Wq,Wk,Wv,Wo
__device__ unsigned char g_inv[M_];
__device__ unsigned int  g_invbits[M_/32];

// ---------------- helpers ---------------------------------------------------
__device__ __forceinline__ float to_tf32(float x) {
    uint32_t r;
    asm("cvt.rna.tf32.f32 %0, %1;" : "=r"(r) : "f"(x));
    return __uint_as_float(r);
}
__device__ __forceinline__ float4 tf32x4(float4 v) {
    return make_float4(to_tf32(v.x), to_tf32(v.y), to_tf32(v.z), to_tf32(v.w));
}
__device__ __forceinline__ uint32_t pack_h2(float lo, float hi) {
    uint32_t r;
    asm("cvt.rn.f16x2.f32 %0, %1, %2;" : "=r"(r) : "f"(hi), "f"(lo));
    return r;
}
__device__ __forceinline__ void mma_tf32(float* d, const uint32_t* a, const uint32_t* b) {
    asm volatile(
        "mma.sync.aligned.m16n8k8.row.col.f32.tf32.tf32.f32 "
        "{%0,%1,%2,%3}, {%4,%5,%6,%7}, {%8,%9}, {%0,%1,%2,%3};\n"
        : "+f"(d[0]), "+f"(d[1]), "+f"(d[2]), "+f"(d[3])
        : "r"(a[0]), "r"(a[1]), "r"(a[2]), "r"(a[3]), "r"(b[0]), "r"(b[1]));
}
__device__ __forceinline__ void mma_f16(float* d, const uint32_t* a, const uint32_t* b) {
    asm volatile(
        "mma.sync.aligned.m16n8k16.row.col.f32.f16.f16.f32 "
        "{%0,%1,%2,%3}, {%4,%5,%6,%7}, {%8,%9}, {%0,%1,%2,%3};\n"
        : "+f"(d[0]), "+f"(d[1]), "+f"(d[2]), "+f"(d[3])
        : "r"(a[0]), "r"(a[1]), "r"(a[2]), "r"(a[3]), "r"(b[0]), "r"(b[1]));
}
__device__ __forceinline__ void cpasync16(void* smem_dst, const void* gptr) {
    uint32_t d = (uint32_t)__cvta_generic_to_shared(smem_dst);
    asm volatile("cp.async.ca.shared.global [%0], [%1], 16;\n" :: "r"(d), "l"(gptr));
}

// ---------------- prep kernels ----------------------------------------------
__global__ void mask_kernel(const int* __restrict__ mask,
                            const int* __restrict__ ncount) {
    int idx = blockIdx.x * 256 + threadIdx.x;
    if (idx < M_) {
        int b = idx >> 9;
        int n = idx & 511;
        bool inv = (mask[2*idx] != 0) || (mask[2*idx+1] != 0) || (n >= ncount[b]);
        g_inv[idx] = inv ? 1 : 0;
        unsigned bal = __ballot_sync(0xffffffffu, inv);
        if ((threadIdx.x & 31) == 0) g_invbits[idx >> 5] = bal;
    }
}

__global__ void round_w_kernel(const float* __restrict__ Wq, const float* __restrict__ Wk,
                               const float* __restrict__ Wv, const float* __restrict__ Wo) {
    int idx = blockIdx.x * 256 + threadIdx.x;     // 65536 float4 slots total
    int m = idx >> 14;                            // matrix 0..3
    int off = (idx & 16383) * 4;
    const float* src = (m == 0) ? Wq : (m == 1) ? Wk : (m == 2) ? Wv : Wo;
    float4 v = *(const float4*)&src[off];
    *(float4*)&g_wr[m*D_*D_ + off] = tf32x4(v);
}

// ---------------- tf32 mma GEMM (validated in R3/R6) -------------------------
#define GSTAGE_FLTS 8960          // As 128*36 + Bs 32*136
#define GEMM_SMEM_BYTES (3*GSTAGE_FLTS*4)

template<bool RES, bool ROUND>
__device__ __forceinline__ void gemm_body(const float* __restrict__ A,
                                          const float* __restrict__ W,
                                          const float* __restrict__ bias,
                                          const float* __restrict__ res,
                                          float* __restrict__ C) {
    extern __shared__ float smem[];

    const int tid  = threadIdx.x;
    const int lane = tid & 31, warp = tid >> 5;
    const int g = lane >> 2, t = lane & 3;
    const int mw = (warp >> 1) * 64, nw = (warp & 1) * 64;
    const int row0 = blockIdx.x * 128, col0 = blockIdx.y * 128;

    const int ar = tid >> 3, ac = (tid & 7) * 4;
    const int br = tid >> 5, bc = (tid & 31) * 4;

    float acc[4][8][4];
#pragma unroll
    for (int i = 0; i < 4; i++)
#pragma unroll
        for (int j = 0; j < 8; j++)
#pragma unroll
            for (int q = 0; q < 4; q++) acc[i][j][q] = 0.f;

    const float* gA = &A[(size_t)(row0 + ar)*D_ + ac];
    const float* gB = &W[(size_t)br*D_ + col0 + bc];

    auto issue = [&](int chunk, int stage) {
        float* As = smem + stage * GSTAGE_FLTS;
        float* Bs = As + 4608;
#pragma unroll
        for (int p = 0; p < 8; p++)
            cpasync16(&As[(ar + 16*p)*36 + ac], gA + (size_t)16*p*D_ + chunk*32);
#pragma unroll
        for (int p = 0; p < 8; p++)
            cpasync16(&Bs[(br + 4*p)*136 + bc], gB + (size_t)(chunk*32 + 4*p)*D_);
        asm volatile("cp.async.commit_group;\n" ::: "memory");
    };

    issue(0, 0);
    issue(1, 1);

    for (int i = 0; i < 8; i++) {
        if (i < 7) asm volatile("cp.async.wait_group 1;\n" ::: "memory");
        else       asm volatile("cp.async.wait_group 0;\n" ::: "memory");
        __syncthreads();
        if (i < 6) issue(i + 2, (i + 2) % 3);

        const float* As = smem + (i % 3) * GSTAGE_FLTS;
        const float* Bs = As + 4608;
#pragma unroll
        for (int ks = 0; ks < 4; ks++) {
            const int k = ks * 8;
            uint32_t af[4][4];
#pragma unroll
            for (int ma = 0; ma < 4; ma++) {
                const float* ab = &As[(mw + ma*16 + g)*36 + k + t];
                af[ma][0] = __float_as_uint(ab[0]);
                af[ma][1] = __float_as_uint(ab[8*36]);
                af[ma][2] = __float_as_uint(ab[4]);
                af[ma][3] = __float_as_uint(ab[8*36 + 4]);
            }
#pragma unroll
            for (int na = 0; na < 8; na++) {
                const float* bb = &Bs[(k + t)*136 + nw + na*8 + g];
                uint32_t bf[2] = {__float_as_uint(bb[0]), __float_as_uint(bb[4*136])};
#pragma unroll
                for (int ma = 0; ma < 4; ma++) mma_tf32(acc[ma][na], af[ma], bf);
            }
        }
        __syncthreads();
    }

#pragma unroll
    for (int ma = 0; ma < 4; ma++) {
        const int r0g = row0 + mw + ma*16 + g;
#pragma unroll
        for (int na = 0; na < 8; na++) {
            const int c0 = col0 + nw + na*8 + 2*t;
            float2 o0, o1;
            o0.x = acc[ma][na][0] + bias[c0];
            o0.y = acc[ma][na][1] + bias[c0+1];
            o1.x = acc[ma][na][2] + bias[c0];
            o1.y = acc[ma][na][3] + bias[c0+1];
            if (RES) {
                float2 ra = *(const float2*)&res[(size_t)r0g*D_ + c0];
                float2 rb = *(const float2*)&res[(size_t)(r0g+8)*D_ + c0];
                o0.x += ra.x; o0.y += ra.y;
                o1.x += rb.x; o1.y += rb.y;
            }
            if (ROUND) {
                o0.x = to_tf32(o0.x); o0.y = to_tf32(o0.y);
                o1.x = to_tf32(o1.x); o1.y = to_tf32(o1.y);
            }
            *(float2*)&C[(size_t)r0g*D_ + c0]     = o0;
            *(float2*)&C[(size_t)(r0g+8)*D_ + c0] = o1;
        }
    }
}

__global__ void __launch_bounds__(128)
qkv_kernel(const float* __restrict__ A,
           const float* __restrict__ bq, const float* __restrict__ bk,
           const float* __restrict__ bv) {
    const int z = blockIdx.z;
    const float* W  = g_wr + z*D_*D_;
    const float* bb = (z == 0) ? bq : (z == 1) ? bk : bv;
    float* C        = (z == 0) ? g_q : (z == 1) ? g_k : g_v;
    gemm_body<false, true>(A, W, bb, nullptr, C);
}

__global__ void __launch_bounds__(128)
oproj_kernel(const float* __restrict__ bo,
             const float* __restrict__ hres, float* __restrict__ out) {
    gemm_body<true, false>(g_ao, g_wr + 3*D_*D_, bo, hres, out);
}

// ---------------- register-flash attention ----------------------------------
// 512 thr / 16 warps; warp = (ma 0..3) x (kspl 0..3): 16 q-rows x 128 keys.
// S in regs; softmax in regs; P packed to fp16 A-frags (FA2 layout identity);
// P@V via m16n8k16 fp16 mma against V^T stored fp16 in smem.
#define VT_STR  520               // halves per dk row (word stride 260 ≡ 4 mod 32)
#define OFF_K   0                 // Ks[512][36] f32
#define OFF_VT  18432             // Vt half[32][520] = 16640 halves = 8320 floats
#define OFF_QS  26752             // Qs[64][36]
#define OFF_OP  29056             // Opart[16 warps][16][40]
#define OFF_MR  39296             // Mred[64][4]
#define OFF_SR  39552             // Sred[64][4]
#define ATTN_SMEM_FLTS 39808
#define ATTN_SMEM_BYTES (ATTN_SMEM_FLTS*4)   // 159,232 B

__global__ void __launch_bounds__(512)
attn_kernel() {
    extern __shared__ float sm[];
    float* Ks   = sm + OFF_K;
    __half* Vth = (__half*)(sm + OFF_VT);
    float* Qs   = sm + OFF_QS;
    float* Op   = sm + OFF_OP;
    float* Mred = sm + OFF_MR;
    float* Sred = sm + OFF_SR;

    const int tid  = threadIdx.x;
    const int lane = tid & 31, warp = tid >> 5;
    const int g = lane >> 2, t = lane & 3;
    const int ma   = warp >> 2;          // q-row atom 0..3
    const int kspl = warp & 3;           // key-split 0..3
    const int bh   = blockIdx.x >> 1;
    const int half = blockIdx.x & 1;
    const int b  = bh >> 3;
    const int hh = bh & 7;

    const float* Qg = g_q  + (size_t)b*N_*D_ + hh*DK_;
    const float* Kg = g_k  + (size_t)b*N_*D_ + hh*DK_;
    const float* Vg = g_v  + (size_t)b*N_*D_ + hh*DK_;
    float*       Og = g_ao + (size_t)b*N_*D_ + hh*DK_;

    // key-invalid bitmask for this warp's 128 keys; pre-shift per thread
    uint32_t invw[4];
#pragma unroll
    for (int j = 0; j < 4; j++)
        invw[j] = g_invbits[b*16 + kspl*4 + j] >> (t << 1);

    // ---- load K (f32 row-major) and V (fp16 transposed [dk][key]) ----
    {
        const int r = tid >> 3, c = (tid & 7) * 4;
#pragma unroll
        for (int p = 0; p < 8; p++) {
            const int key = r + 64*p;
            float4 kv = *(const float4*)&Kg[(size_t)key*D_ + c];
            *(float4*)&Ks[key*36 + c] = kv;
            float4 vv = *(const float4*)&Vg[(size_t)key*D_ + c];
            Vth[(c+0)*VT_STR + key] = __float2half_rn(vv.x);
            Vth[(c+1)*VT_STR + key] = __float2half_rn(vv.y);
            Vth[(c+2)*VT_STR + key] = __float2half_rn(vv.z);
            Vth[(c+3)*VT_STR + key] = __float2half_rn(vv.w);
        }
    }

    const float rscale = 0.17677669529663689f;  // 1/sqrt(32)
    const int kb0 = kspl * 128;
    const int rr0 = ma*16 + g;                   // row within 64-row tile
    const uint32_t FULL = 0xffffffffu;

    for (int qt = 0; qt < 4; qt++) {
        const int q0 = half*256 + qt*64;

        // ---- stage Q tile 64x32 ----
        __syncthreads();     // Opart/Qs free (also covers initial K/V load at qt=0)
        {
            const int r = tid >> 3, c = (tid & 7) * 4;
            *(float4*)&Qs[r*36 + c] = *(const float4*)&Qg[(size_t)(q0 + r)*D_ + c];
        }
        __syncthreads();

        // query-invalid flags for this thread's two rows
        const bool iq0 = g_inv[b*N_ + q0 + rr0]     != 0;
        const bool iq1 = g_inv[b*N_ + q0 + rr0 + 8] != 0;

        // ---- phase A: S[16 x 128] = Q @ K^T in registers (tf32) ----
        uint32_t af[4][4];
#pragma unroll
        for (int ko = 0; ko < 4; ko++) {
            const float* ab = &Qs[rr0*36 + ko*8 + t];
            af[ko][0] = __float_as_uint(ab[0]);
            af[ko][1] = __float_as_uint(ab[8*36]);
            af[ko][2] = __float_as_uint(ab[4]);
            af[ko][3] = __float_as_uint(ab[8*36 + 4]);
        }

        float acc[16][4];
#pragma unroll
        for (int na = 0; na < 16; na++) {
            acc[na][0] = acc[na][1] = acc[na][2] = acc[na][3] = 0.f;
#pragma unroll
            for (int ko = 0; ko < 4; ko++) {
                const float* bb = &Ks[(kb0 + na*8 + g)*36 + ko*8 + t];
                uint32_t bf[2] = {__float_as_uint(bb[0]), __float_as_uint(bb[4])};
                mma_tf32(acc[na], af[ko], bf);
            }
        }

        // ---- mask + scale (regs), per-warp row max ----
        float mx0 = -1e30f, mx1 = -1e30f;
#pragma unroll
        for (int na = 0; na < 16; na++) {
            const uint32_t w = invw[na >> 2] >> ((na & 3) << 3);
            const bool ik0 = (w & 1u) != 0;
            const bool ik1 = (w & 2u) != 0;
            acc[na][0] = (iq0 || ik0) ? -1e9f : acc[na][0] * rscale;
            acc[na][1] = (iq0 || ik1) ? -1e9f : acc[na][1] * rscale;
            acc[na][2] = (iq1 || ik0) ? -1e9f : acc[na][2] * rscale;
            acc[na][3] = (iq1 || ik1) ? -1e9f : acc[na][3] * rscale;
            mx0 = fmaxf(mx0, fmaxf(acc[na][0], acc[na][1]));
            mx1 = fmaxf(mx1, fmaxf(acc[na][2], acc[na][3]));
        }
        mx0 = fmaxf(mx0, __shfl_xor_sync(FULL, mx0, 1));
        mx0 = fmaxf(mx0, __shfl_xor_sync(FULL, mx0, 2));
        mx1 = fmaxf(mx1, __shfl_xor_sync(FULL, mx1, 1));
        mx1 = fmaxf(mx1, __shfl_xor_sync(FULL, mx1, 2));
        if (t == 0) {
            Mred[rr0*4 + kspl]     = mx0;
            Mred[(rr0+8)*4 + kspl] = mx1;
        }
        __syncthreads();

        // global row max
        float4 m4a = *(float4*)&Mred[rr0*4];
        float4 m4b = *(float4*)&Mred[(rr0+8)*4];
        const float M0 = fmaxf(fmaxf(m4a.x, m4a.y), fmaxf(m4a.z, m4a.w));
        const float M1 = fmaxf(fmaxf(m4b.x, m4b.y), fmaxf(m4b.z, m4b.w));

        // ---- exp + row sum (regs), pack P to fp16 A-fragments ----
        uint32_t ph[16][2];
        float sm0 = 0.f, sm1 = 0.f;
#pragma unroll
        for (int na = 0; na < 16; na++) {
            float e0 = __expf(acc[na][0] - M0);
            float e1 = __expf(acc[na][1] - M0);
            float e2 = __expf(acc[na][2] - M1);
            float e3 = __expf(acc[na][3] - M1);
            sm0 += e0 + e1;
            sm1 += e2 + e3;
            ph[na][0] = pack_h2(e0, e1);   // rows g,   cols 8na+2t, +1
            ph[na][1] = pack_h2(e2, e3);   // rows g+8
        }
        sm0 += __shfl_xor_sync(FULL, sm0, 1);
        sm0 += __shfl_xor_sync(FULL, sm0, 2);
        sm1 += __shfl_xor_sync(FULL, sm1, 1);
        sm1 += __shfl_xor_sync(FULL, sm1, 2);
        if (t == 0) {
            Sred[rr0*4 + kspl]     = sm0;
            Sred[(rr0+8)*4 + kspl] = sm1;
        }

        // ---- phase 3: O_partial[16 x 32] = P @ V, fp16 m16n8k16 ----
        float oacc[4][4];
#pragma unroll
        for (int na = 0; na < 4; na++)
#pragma unroll
            for (int q = 0; q < 4; q++) oacc[na][q] = 0.f;

#pragma unroll
        for (int j = 0; j < 8; j++) {
            uint32_t pa[4] = { ph[2*j][0], ph[2*j][1], ph[2*j+1][0], ph[2*j+1][1] };
            const int kk = kb0 + 16*j + 2*t;
#pragma unroll
            for (int na = 0; na < 4; na++) {
                const __half* bb = Vth + (na*8 + g)*VT_STR + kk;
                uint32_t bf[2] = { *(const uint32_t*)bb, *(const uint32_t*)(bb + 8) };
                mma_f16(oacc[na], pa, bf);
            }
        }

        // ---- store partials ----
        {
            float* op = Op + warp * 640;
#pragma unroll
            for (int na = 0; na < 4; na++) {
                const int c = na*8 + 2*t;
                *(float2*)&op[g*40 + c]     = make_float2(oacc[na][0], oacc[na][1]);
                *(float2*)&op[(g+8)*40 + c] = make_float2(oacc[na][2], oacc[na][3]);
            }
        }
        __syncthreads();

        // ---- combine 4 key-split partials, normalize, store ----
        {
            const int r  = tid >> 3;            // 0..63
            const int c4 = (tid & 7) * 4;       // 0..28
            const int wb = (r >> 4) * 4;        // ma*4
            const int rl = r & 15;
            float4 o = {0.f, 0.f, 0.f, 0.f};
#pragma unroll
            for (int kk = 0; kk < 4; kk++) {
                float4 p = *(float4*)&Op[(wb + kk)*640 + rl*40 + c4];
                o.x += p.x; o.y += p.y; o.z += p.z; o.w += p.w;
            }
            float4 s4 = *(float4*)&Sred[r*4];
            const float rs = 1.0f / (s4.x + s4.y + s4.z + s4.w);
            float4 ov = make_float4(to_tf32(o.x*rs), to_tf32(o.y*rs),
                                    to_tf32(o.z*rs), to_tf32(o.w*rs));
            *(float4*)&Og[(size_t)(q0 + r)*D_ + c4] = ov;
        }
    }
}

// ---------------- launcher --------------------------------------------------
extern "C" void kernel_launch(void* const* d_in, const int* in_sizes, int n_in,
                              void* d_out, int out_size) {
    const float* h    = (const float*)d_in[0];
    const int*   mask = (const int*)  d_in[1];
    const int*   nc   = (const int*)  d_in[2];
    const float* Wq   = (const float*)d_in[3];
    const float* bq   = (const float*)d_in[4];
    const float* Wk   = (const float*)d_in[5];
    const float* bk   = (const float*)d_in[6];
    const float* Wv   = (const float*)d_in[7];
    const float* bv   = (const float*)d_in[8];
    const float* Wo   = (const float*)d_in[9];
    const float* bo   = (const float*)d_in[10];
    float* out = (float*)d_out;

    cudaFuncSetAttribute(attn_kernel, cudaFuncAttributeMaxDynamicSharedMemorySize,
                         ATTN_SMEM_BYTES);
    cudaFuncSetAttribute(qkv_kernel, cudaFuncAttributeMaxDynamicSharedMemorySize,
                         GEMM_SMEM_BYTES);
    cudaFuncSetAttribute(oproj_kernel, cudaFuncAttributeMaxDynamicSharedMemorySize,
                         GEMM_SMEM_BYTES);

    mask_kernel<<<M_/256, 256>>>(mask, nc);
    round_w_kernel<<<256, 256>>>(Wq, Wk, Wv, Wo);
    qkv_kernel<<<dim3(M_/128, D_/128, 3), 128, GEMM_SMEM_BYTES>>>(h, bq, bk, bv);
    attn_kernel<<<B_*H_*2, 512, ATTN_SMEM_BYTES>>>();
    oproj_kernel<<<dim3(M_/128, D_/128), 128, GEMM_SMEM_BYTES>>>(bo, h, out);
}

// round 11
// speedup vs baseline: 3.7088x; 1.0718x over previous
#include <cuda_runtime.h>
#include <cuda_fp16.h>
#include <math.h>
#include <stdint.h>

#define B_  64
#define N_  512
#define D_  256
#define H_  8
#define DK_ 32
#define M_  (B_*N_)   // 32768

// Q pre-scale: (1/sqrt(DK)) * log2(e)  -> softmax done in exp2 domain
#define QSCALE 0.25502421277695494f

// ---------------- scratch (static device globals; no allocation) ----------
__device__ __align__(256) __half g_qh[M_*D_];
__device__ __align__(256) __half g_kh[M_*D_];
__device__ __align__(256) float  g_v [M_*D_];
__device__ __align__(256) float  g_ao[M_*D_];
__device__ __align__(256) float  g_wr[4*D_*D_];   // tf32-rounded Wq,Wk,Wv,Wo
__device__ unsigned char g_inv[M_];
__device__ unsigned int  g_invbits[M_/32];

// ---------------- helpers ---------------------------------------------------
__device__ __forceinline__ float to_tf32(float x) {
    uint32_t r;
    asm("cvt.rna.tf32.f32 %0, %1;" : "=r"(r) : "f"(x));
    return __uint_as_float(r);
}
__device__ __forceinline__ float4 tf32x4(float4 v) {
    return make_float4(to_tf32(v.x), to_tf32(v.y), to_tf32(v.z), to_tf32(v.w));
}
__device__ __forceinline__ uint32_t pack_h2(float lo, float hi) {
    uint32_t r;
    asm("cvt.rn.f16x2.f32 %0, %1, %2;" : "=r"(r) : "f"(hi), "f"(lo));
    return r;
}
__device__ __forceinline__ float ex2f(float x) {
    float r;
    asm("ex2.approx.f32 %0, %1;" : "=f"(r) : "f"(x));
    return r;
}
__device__ __forceinline__ void mma_tf32(float* d, const uint32_t* a, const uint32_t* b) {
    asm volatile(
        "mma.sync.aligned.m16n8k8.row.col.f32.tf32.tf32.f32 "
        "{%0,%1,%2,%3}, {%4,%5,%6,%7}, {%8,%9}, {%0,%1,%2,%3};\n"
        : "+f"(d[0]), "+f"(d[1]), "+f"(d[2]), "+f"(d[3])
        : "r"(a[0]), "r"(a[1]), "r"(a[2]), "r"(a[3]), "r"(b[0]), "r"(b[1]));
}
__device__ __forceinline__ void mma_f16(float* d, const uint32_t* a, const uint32_t* b) {
    asm volatile(
        "mma.sync.aligned.m16n8k16.row.col.f32.f16.f16.f32 "
        "{%0,%1,%2,%3}, {%4,%5,%6,%7}, {%8,%9}, {%0,%1,%2,%3};\n"
        : "+f"(d[0]), "+f"(d[1]), "+f"(d[2]), "+f"(d[3])
        : "r"(a[0]), "r"(a[1]), "r"(a[2]), "r"(a[3]), "r"(b[0]), "r"(b[1]));
}
__device__ __forceinline__ void ldsm_x4(uint32_t& r0, uint32_t& r1, uint32_t& r2,
                                        uint32_t& r3, uint32_t saddr) {
    asm volatile("ldmatrix.sync.aligned.m8n8.x4.shared.b16 {%0,%1,%2,%3}, [%4];"
                 : "=r"(r0), "=r"(r1), "=r"(r2), "=r"(r3) : "r"(saddr));
}
__device__ __forceinline__ void cpasync16(void* smem_dst, const void* gptr) {
    uint32_t d = (uint32_t)__cvta_generic_to_shared(smem_dst);
    asm volatile("cp.async.ca.shared.global [%0], [%1], 16;\n" :: "r"(d), "l"(gptr));
}

// ---------------- prep kernels ----------------------------------------------
__global__ void mask_kernel(const int* __restrict__ mask,
                            const int* __restrict__ ncount) {
    const int idx = blockIdx.x * 256 + threadIdx.x;
    if (idx < M_) {
        const int b = idx >> 9;
        const int n = idx & 511;
        const bool inv = (mask[2*idx] != 0) || (mask[2*idx+1] != 0) || (n >= ncount[b]);
        g_inv[idx] = inv ? 1 : 0;
        const unsigned bal = __ballot_sync(0xffffffffu, inv);
        if ((threadIdx.x & 31) == 0) g_invbits[idx >> 5] = bal;
    }
}

__global__ void round_w_kernel(const float* __restrict__ Wq, const float* __restrict__ Wk,
                               const float* __restrict__ Wv, const float* __restrict__ Wo) {
    const int idx = blockIdx.x * 256 + threadIdx.x;   // 65536 float4 slots total
    const int m = idx >> 14;                          // matrix 0..3
    const int off = (idx & 16383) * 4;
    const float* src = (m == 0) ? Wq : (m == 1) ? Wk : (m == 2) ? Wv : Wo;
    const float4 v = *(const float4*)&src[off];
    *(float4*)&g_wr[m*D_*D_ + off] = tf32x4(v);
}

// ---------------- tf32 mma GEMM core (validated R3/R6/R7) --------------------
// OUT: 0 = f32 + bias + res (oproj), 1 = f32 + bias (V), 2 = half, (acc+bias)*scale
#define GSTAGE_FLTS 8960          // As 128*36 + Bs 32*136
#define GEMM_SMEM_BYTES (3*GSTAGE_FLTS*4)

template<int OUT>
__device__ __forceinline__ void gemm_body(const float* __restrict__ A,
                                          const float* __restrict__ W,
                                          const float* __restrict__ bias,
                                          const float* __restrict__ res,
                                          float* __restrict__ Cf,
                                          __half* __restrict__ Ch,
                                          float scale) {
    extern __shared__ float smem[];

    const int tid  = threadIdx.x;
    const int lane = tid & 31, warp = tid >> 5;
    const int g = lane >> 2, t = lane & 3;
    const int mw = (warp >> 1) * 64, nw = (warp & 1) * 64;
    const int row0 = blockIdx.x * 128, col0 = blockIdx.y * 128;

    const int ar = tid >> 3, ac = (tid & 7) * 4;
    const int br = tid >> 5, bc = (tid & 31) * 4;

    float acc[4][8][4];
#pragma unroll
    for (int i = 0; i < 4; i++)
#pragma unroll
        for (int j = 0; j < 8; j++)
#pragma unroll
            for (int q = 0; q < 4; q++) acc[i][j][q] = 0.f;

    const float* gA = &A[(size_t)(row0 + ar)*D_ + ac];
    const float* gB = &W[(size_t)br*D_ + col0 + bc];

    auto issue = [&](int chunk, int stage) {
        float* As = smem + stage * GSTAGE_FLTS;
        float* Bs = As + 4608;
#pragma unroll
        for (int p = 0; p < 8; p++)
            cpasync16(&As[(ar + 16*p)*36 + ac], gA + (size_t)16*p*D_ + chunk*32);
#pragma unroll
        for (int p = 0; p < 8; p++)
            cpasync16(&Bs[(br + 4*p)*136 + bc], gB + (size_t)(chunk*32 + 4*p)*D_);
        asm volatile("cp.async.commit_group;\n" ::: "memory");
    };

    issue(0, 0);
    issue(1, 1);

    for (int i = 0; i < 8; i++) {
        if (i < 7) asm volatile("cp.async.wait_group 1;\n" ::: "memory");
        else       asm volatile("cp.async.wait_group 0;\n" ::: "memory");
        __syncthreads();
        if (i < 6) issue(i + 2, (i + 2) % 3);

        const float* As = smem + (i % 3) * GSTAGE_FLTS;
        const float* Bs = As + 4608;
#pragma unroll
        for (int ks = 0; ks < 4; ks++) {
            const int k = ks * 8;
            uint32_t af[4][4];
#pragma unroll
            for (int ma = 0; ma < 4; ma++) {
                const float* ab = &As[(mw + ma*16 + g)*36 + k + t];
                af[ma][0] = __float_as_uint(ab[0]);
                af[ma][1] = __float_as_uint(ab[8*36]);
                af[ma][2] = __float_as_uint(ab[4]);
                af[ma][3] = __float_as_uint(ab[8*36 + 4]);
            }
#pragma unroll
            for (int na = 0; na < 8; na++) {
                const float* bb = &Bs[(k + t)*136 + nw + na*8 + g];
                uint32_t bf[2] = {__float_as_uint(bb[0]), __float_as_uint(bb[4*136])};
#pragma unroll
                for (int ma = 0; ma < 4; ma++) mma_tf32(acc[ma][na], af[ma], bf);
            }
        }
        __syncthreads();
    }

#pragma unroll
    for (int ma = 0; ma < 4; ma++) {
        const int r0g = row0 + mw + ma*16 + g;
#pragma unroll
        for (int na = 0; na < 8; na++) {
            const int c0 = col0 + nw + na*8 + 2*t;
            float2 o0, o1;
            o0.x = acc[ma][na][0] + bias[c0];
            o0.y = acc[ma][na][1] + bias[c0+1];
            o1.x = acc[ma][na][2] + bias[c0];
            o1.y = acc[ma][na][3] + bias[c0+1];
            if (OUT == 2) {
                *(uint32_t*)&Ch[(size_t)r0g*D_ + c0]     = pack_h2(o0.x*scale, o0.y*scale);
                *(uint32_t*)&Ch[(size_t)(r0g+8)*D_ + c0] = pack_h2(o1.x*scale, o1.y*scale);
            } else {
                if (OUT == 0) {
                    const float2 ra = *(const float2*)&res[(size_t)r0g*D_ + c0];
                    const float2 rb = *(const float2*)&res[(size_t)(r0g+8)*D_ + c0];
                    o0.x += ra.x; o0.y += ra.y;
                    o1.x += rb.x; o1.y += rb.y;
                }
                *(float2*)&Cf[(size_t)r0g*D_ + c0]     = o0;
                *(float2*)&Cf[(size_t)(r0g+8)*D_ + c0] = o1;
            }
        }
    }
}

__global__ void __launch_bounds__(128)
qk_kernel(const float* __restrict__ A,
          const float* __restrict__ bq, const float* __restrict__ bk) {
    const int z = blockIdx.z;   // 0=Q, 1=K
    gemm_body<2>(A, g_wr + z*D_*D_, z ? bk : bq, nullptr, nullptr,
                 z ? g_kh : g_qh, z ? 1.0f : QSCALE);
}

__global__ void __launch_bounds__(128)
v_kernel(const float* __restrict__ A, const float* __restrict__ bv) {
    gemm_body<1>(A, g_wr + 2*D_*D_, bv, nullptr, g_v, nullptr, 1.0f);
}

__global__ void __launch_bounds__(128)
oproj_kernel(const float* __restrict__ bo,
             const float* __restrict__ hres, float* __restrict__ out) {
    gemm_body<0>(g_ao, g_wr + 3*D_*D_, bo, hres, out, nullptr, 1.0f);
}

// ---------------- register-flash attention (fp16 QK + fp16 PV) --------------
// 512 thr / 16 warps; warp = (ma 0..3) x (kspl 0..3): 16 q-rows x 128 keys.
// Phase1: m16n8k16 fp16 mma; A/B frags via NON-trans ldmatrix (B-frag of
// row.col mma from row-major K needs key-on-g, dk-on-t = non-trans layout;
// matches the validated tf32 path's bf[0]=K[key=g][k+t] contract).
// Softmax in exp2 domain (log2e folded into Q). Phase3: fp16 PV (R7 identity).
#define KH_STR  40                // halves per K/Q smem row (80 B, cf-free ldsm)
#define VT_STR  520               // halves per dk row of V^T
#define OFFB_K  0                 // Kh[512][40]h  = 40960 B
#define OFFB_VT 40960             // Vt[32][520]h  = 33280 B
#define OFFB_Q  74240             // Qh[64][40]h   = 5120 B
#define OFFB_OP 79360             // Op[16][16][40]f = 40960 B
#define OFFB_MR 120320            // Mred[64][4]f
#define OFFB_SR 121344            // Sred[64][4]f
#define ATTN_SMEM_BYTES 122368

__global__ void __launch_bounds__(512)
attn_kernel() {
    extern __shared__ char smc[];
    __half* Khs  = (__half*)(smc + OFFB_K);
    __half* Vth  = (__half*)(smc + OFFB_VT);
    __half* Qhs  = (__half*)(smc + OFFB_Q);
    float*  Op   = (float*) (smc + OFFB_OP);
    float*  Mred = (float*) (smc + OFFB_MR);
    float*  Sred = (float*) (smc + OFFB_SR);
    const uint32_t sb = (uint32_t)__cvta_generic_to_shared(smc);

    const int tid  = threadIdx.x;
    const int lane = tid & 31;
    const int warp = tid >> 5;
    const int g = lane >> 2, t = lane & 3;
    const int lrow = lane & 7, grp = lane >> 3;
    const int ma   = warp >> 2;          // q-row atom 0..3
    const int kspl = warp & 3;           // key-split 0..3
    const int bh   = blockIdx.x >> 1;
    const int half = blockIdx.x & 1;
    const int b  = bh >> 3;
    const int hh = bh & 7;

    const __half* Qg = g_qh + (size_t)b*N_*D_ + hh*DK_;
    const __half* Kg = g_kh + (size_t)b*N_*D_ + hh*DK_;
    const float*  Vg = g_v  + (size_t)b*N_*D_ + hh*DK_;
    float*        Og = g_ao + (size_t)b*N_*D_ + hh*DK_;

    // key-invalid bitmask for this warp's 128 keys; pre-shift per thread
    uint32_t invw[4];
#pragma unroll
    for (int j = 0; j < 4; j++)
        invw[j] = g_invbits[b*16 + kspl*4 + j] >> (t << 1);

    // ---- load K (fp16 row-major, stride 40h) and V (fp16 transposed) ----
    {
        const int r = tid >> 3, cg = (tid & 7) * 4;     // 4 halves per thread
#pragma unroll
        for (int p = 0; p < 8; p++) {
            const int key = r + 64*p;
            *(uint2*)&Khs[key*KH_STR + cg] = *(const uint2*)&Kg[(size_t)key*D_ + cg];
            const float4 vv = *(const float4*)&Vg[(size_t)key*D_ + cg];
            Vth[(cg+0)*VT_STR + key] = __float2half_rn(vv.x);
            Vth[(cg+1)*VT_STR + key] = __float2half_rn(vv.y);
            Vth[(cg+2)*VT_STR + key] = __float2half_rn(vv.z);
            Vth[(cg+3)*VT_STR + key] = __float2half_rn(vv.w);
        }
    }

    const int kb0 = kspl * 128;
    const int rr0 = ma*16 + g;                   // row within 64-row tile
    const uint32_t FULL = 0xffffffffu;

    // ldmatrix base addresses (byte offsets in smem), all NON-trans:
    // Q A-frags: m_off=(grp&1)*8 rows, k_off=(grp>>1)*8 halves
    //   -> regs {r0-7/k0-7, r8-15/k0-7, r0-7/k8-15, r8-15/k8-15} = {a0,a1,a2,a3}
    const uint32_t qa_base = sb + OFFB_Q
        + (uint32_t)(((ma*16 + (grp&1)*8 + lrow)*KH_STR + (grp>>1)*8) * 2);
    // K B-frags: key_off=(grp>>1)*8 rows, dk_off=(grp&1)*8 halves
    //   -> regs {keys0-7/dk0-7, keys0-7/dk8-15, keys8-15/dk0-7, keys8-15/dk8-15}
    //      = {b0,b1} octet0, {b0,b1} octet1
    const uint32_t ka_row  = (uint32_t)((grp>>1)*8 + lrow);
    const uint32_t ka_koff = (uint32_t)((grp&1)*8);

    for (int qt = 0; qt < 4; qt++) {
        const int q0 = half*256 + qt*64;

        // ---- stage Q tile 64x32 fp16 ----
        __syncthreads();     // Op/Qhs free (also covers initial K/V load at qt=0)
        {
            const int r = tid >> 3, cg = (tid & 7) * 4;
            *(uint2*)&Qhs[r*KH_STR + cg] = *(const uint2*)&Qg[(size_t)(q0 + r)*D_ + cg];
        }
        __syncthreads();

        // query-invalid flags for this thread's two rows
        const bool iq0 = g_inv[b*N_ + q0 + rr0]     != 0;
        const bool iq1 = g_inv[b*N_ + q0 + rr0 + 8] != 0;

        // ---- phase 1: S[16 x 128] = Q @ K^T, fp16 m16n8k16 ----
        uint32_t aq[2][4];
        ldsm_x4(aq[0][0], aq[0][1], aq[0][2], aq[0][3], qa_base);
        ldsm_x4(aq[1][0], aq[1][1], aq[1][2], aq[1][3], qa_base + 32);

        float acc[16][4];
#pragma unroll
        for (int j = 0; j < 8; j++) {
            const uint32_t kaddr = sb + OFFB_K
                + (uint32_t)((((kb0 + j*16) + ka_row)*KH_STR + ka_koff) * 2);
            uint32_t kb[4], kc[4];
            ldsm_x4(kb[0], kb[1], kb[2], kb[3], kaddr);        // dk 0-15
            ldsm_x4(kc[0], kc[1], kc[2], kc[3], kaddr + 32);   // dk 16-31
            acc[2*j][0] = acc[2*j][1] = acc[2*j][2] = acc[2*j][3] = 0.f;
            acc[2*j+1][0] = acc[2*j+1][1] = acc[2*j+1][2] = acc[2*j+1][3] = 0.f;
            mma_f16(acc[2*j],   aq[0], kb);       // octet0 (keys j16+0-7),  k0-15
            mma_f16(acc[2*j],   aq[1], kc);       // octet0, k16-31
            mma_f16(acc[2*j+1], aq[0], kb + 2);   // octet1 (keys j16+8-15), k0-15
            mma_f16(acc[2*j+1], aq[1], kc + 2);   // octet1, k16-31
        }

        // ---- mask (regs), per-warp row max ----
        float mx0 = -1e30f, mx1 = -1e30f;
#pragma unroll
        for (int na = 0; na < 16; na++) {
            const uint32_t w = invw[na >> 2] >> ((na & 3) << 3);
            const bool ik0 = (w & 1u) != 0;
            const bool ik1 = (w & 2u) != 0;
            acc[na][0] = (iq0 || ik0) ? -1e9f : acc[na][0];
            acc[na][1] = (iq0 || ik1) ? -1e9f : acc[na][1];
            acc[na][2] = (iq1 || ik0) ? -1e9f : acc[na][2];
            acc[na][3] = (iq1 || ik1) ? -1e9f : acc[na][3];
            mx0 = fmaxf(mx0, fmaxf(acc[na][0], acc[na][1]));
            mx1 = fmaxf(mx1, fmaxf(acc[na][2], acc[na][3]));
        }
        mx0 = fmaxf(mx0, __shfl_xor_sync(FULL, mx0, 1));
        mx0 = fmaxf(mx0, __shfl_xor_sync(FULL, mx0, 2));
        mx1 = fmaxf(mx1, __shfl_xor_sync(FULL, mx1, 1));
        mx1 = fmaxf(mx1, __shfl_xor_sync(FULL, mx1, 2));
        if (t == 0) {
            Mred[rr0*4 + kspl]     = mx0;
            Mred[(rr0+8)*4 + kspl] = mx1;
        }
        __syncthreads();

        // global row max (exp2 domain)
        const float4 m4a = *(float4*)&Mred[rr0*4];
        const float4 m4b = *(float4*)&Mred[(rr0+8)*4];
        const float M0 = fmaxf(fmaxf(m4a.x, m4a.y), fmaxf(m4a.z, m4a.w));
        const float M1 = fmaxf(fmaxf(m4b.x, m4b.y), fmaxf(m4b.z, m4b.w));

        // ---- exp2 + row sum (regs), pack P to fp16 A-fragments ----
        uint32_t ph[16][2];
        float sm0 = 0.f, sm1 = 0.f;
#pragma unroll
        for (int na = 0; na < 16; na++) {
            const float e0 = ex2f(acc[na][0] - M0);
            const float e1 = ex2f(acc[na][1] - M0);
            const float e2 = ex2f(acc[na][2] - M1);
            const float e3 = ex2f(acc[na][3] - M1);
            sm0 += e0 + e1;
            sm1 += e2 + e3;
            ph[na][0] = pack_h2(e0, e1);   // rows g,   cols 8na+2t, +1
            ph[na][1] = pack_h2(e2, e3);   // rows g+8
        }
        sm0 += __shfl_xor_sync(FULL, sm0, 1);
        sm0 += __shfl_xor_sync(FULL, sm0, 2);
        sm1 += __shfl_xor_sync(FULL, sm1, 1);
        sm1 += __shfl_xor_sync(FULL, sm1, 2);
        if (t == 0) {
            Sred[rr0*4 + kspl]     = sm0;
            Sred[(rr0+8)*4 + kspl] = sm1;
        }

        // ---- phase 3: O_partial[16 x 32] = P @ V, fp16 m16n8k16 ----
        float oacc[4][4];
#pragma unroll
        for (int na = 0; na < 4; na++)
#pragma unroll
            for (int q = 0; q < 4; q++) oacc[na][q] = 0.f;

#pragma unroll
        for (int j = 0; j < 8; j++) {
            const uint32_t pa[4] = { ph[2*j][0], ph[2*j][1], ph[2*j+1][0], ph[2*j+1][1] };
            const int kk = kb0 + 16*j + 2*t;
#pragma unroll
            for (int na = 0; na < 4; na++) {
                const __half* bb = Vth + (na*8 + g)*VT_STR + kk;
                uint32_t bf[2] = { *(const uint32_t*)bb, *(const uint32_t*)(bb + 8) };
                mma_f16(oacc[na], pa, bf);
            }
        }

        // ---- store partials ----
        {
            float* op = Op + warp * 640;
#pragma unroll
            for (int na = 0; na < 4; na++) {
                const int c = na*8 + 2*t;
                *(float2*)&op[g*40 + c]     = make_float2(oacc[na][0], oacc[na][1]);
                *(float2*)&op[(g+8)*40 + c] = make_float2(oacc[na][2], oacc[na][3]);
            }
        }
        __syncthreads();

        // ---- combine 4 key-split partials, normalize, store ----
        {
            const int r  = tid >> 3;            // 0..63
            const int c4 = (tid & 7) * 4;       // 0..28
            const int wb = (r >> 4) * 4;        // ma*4
            const int rl = r & 15;
            float4 o = {0.f, 0.f, 0.f, 0.f};
#pragma unroll
            for (int kk = 0; kk < 4; kk++) {
                const float4 p = *(float4*)&Op[(wb + kk)*640 + rl*40 + c4];
                o.x += p.x; o.y += p.y; o.z += p.z; o.w += p.w;
            }
            const float4 s4 = *(float4*)&Sred[r*4];
            const float rs = 1.0f / (s4.x + s4.y + s4.z + s4.w);
            const float4 ov = make_float4(o.x*rs, o.y*rs, o.z*rs, o.w*rs);
            *(float4*)&Og[(size_t)(q0 + r)*D_ + c4] = ov;
        }
    }
}

// ---------------- launcher --------------------------------------------------
extern "C" void kernel_launch(void* const* d_in, const int* in_sizes, int n_in,
                              void* d_out, int out_size) {
    const float* h    = (const float*)d_in[0];
    const int*   mask = (const int*)  d_in[1];
    const int*   nc   = (const int*)  d_in[2];
    const float* Wq   = (const float*)d_in[3];
    const float* bq   = (const float*)d_in[4];
    const float* Wk   = (const float*)d_in[5];
    const float* bk   = (const float*)d_in[6];
    const float* Wv   = (const float*)d_in[7];
    const float* bv   = (const float*)d_in[8];
    const float* Wo   = (const float*)d_in[9];
    const float* bo   = (const float*)d_in[10];
    float* out = (float*)d_out;

    cudaFuncSetAttribute(attn_kernel, cudaFuncAttributeMaxDynamicSharedMemorySize,
                         ATTN_SMEM_BYTES);
    cudaFuncSetAttribute(qk_kernel, cudaFuncAttributeMaxDynamicSharedMemorySize,
                         GEMM_SMEM_BYTES);
    cudaFuncSetAttribute(v_kernel, cudaFuncAttributeMaxDynamicSharedMemorySize,
                         GEMM_SMEM_BYTES);
    cudaFuncSetAttribute(oproj_kernel, cudaFuncAttributeMaxDynamicSharedMemorySize,
                         GEMM_SMEM_BYTES);

    mask_kernel<<<M_/256, 256>>>(mask, nc);
    round_w_kernel<<<256, 256>>>(Wq, Wk, Wv, Wo);
    qk_kernel<<<dim3(M_/128, D_/128, 2), 128, GEMM_SMEM_BYTES>>>(h, bq, bk);
    v_kernel<<<dim3(M_/128, D_/128), 128, GEMM_SMEM_BYTES>>>(h, bv);
    attn_kernel<<<B_*H_*2, 512, ATTN_SMEM_BYTES>>>();
    oproj_kernel<<<dim3(M_/128, D_/128), 128, GEMM_SMEM_BYTES>>>(bo, h, out);
}

// round 12
// speedup vs baseline: 4.8303x; 1.3024x over previous
#include <cuda_runtime.h>
#include <cuda_fp16.h>
#include <math.h>
#include <stdint.h>

#define B_  64
#define N_  512
#define D_  256
#define H_  8
#define DK_ 32
#define M_  (B_*N_)   // 32768

// Q pre-scale: (1/sqrt(DK)) * log2(e)  -> softmax done in exp2 domain
#define QSCALE 0.25502421277695494f

// ---------------- scratch (static device globals; no allocation) ----------
__device__ __align__(256) __half g_hh[M_*D_];     // h in fp16
__device__ __align__(256) __half g_qh[M_*D_];
__device__ __align__(256) __half g_kh[M_*D_];
__device__ __align__(256) __half g_vh[M_*D_];
__device__ __align__(256) __half g_aoh[M_*D_];    // attention output fp16
__device__ __align__(256) __half g_wt[4*D_*D_];   // fp16 W^T (n-major) x4
__device__ unsigned char g_inv[M_];
__device__ unsigned int  g_invbits[M_/32];

// ---------------- helpers ---------------------------------------------------
__device__ __forceinline__ uint32_t pack_h2(float lo, float hi) {
    uint32_t r;
    asm("cvt.rn.f16x2.f32 %0, %1, %2;" : "=r"(r) : "f"(hi), "f"(lo));
    return r;
}
__device__ __forceinline__ float ex2f(float x) {
    float r;
    asm("ex2.approx.f32 %0, %1;" : "=f"(r) : "f"(x));
    return r;
}
__device__ __forceinline__ void mma_f16(float* d, const uint32_t* a, const uint32_t* b) {
    asm volatile(
        "mma.sync.aligned.m16n8k16.row.col.f32.f16.f16.f32 "
        "{%0,%1,%2,%3}, {%4,%5,%6,%7}, {%8,%9}, {%0,%1,%2,%3};\n"
        : "+f"(d[0]), "+f"(d[1]), "+f"(d[2]), "+f"(d[3])
        : "r"(a[0]), "r"(a[1]), "r"(a[2]), "r"(a[3]), "r"(b[0]), "r"(b[1]));
}
__device__ __forceinline__ void ldsm_x4(uint32_t& r0, uint32_t& r1, uint32_t& r2,
                                        uint32_t& r3, uint32_t saddr) {
    asm volatile("ldmatrix.sync.aligned.m8n8.x4.shared.b16 {%0,%1,%2,%3}, [%4];"
                 : "=r"(r0), "=r"(r1), "=r"(r2), "=r"(r3) : "r"(saddr));
}
__device__ __forceinline__ void cpasync16(void* smem_dst, const void* gptr) {
    uint32_t d = (uint32_t)__cvta_generic_to_shared(smem_dst);
    asm volatile("cp.async.ca.shared.global [%0], [%1], 16;\n" :: "r"(d), "l"(gptr));
}

// ---------------- prep kernels ----------------------------------------------
__global__ void mask_kernel(const int* __restrict__ mask,
                            const int* __restrict__ ncount) {
    const int idx = blockIdx.x * 256 + threadIdx.x;
    if (idx < M_) {
        const int b = idx >> 9;
        const int n = idx & 511;
        const bool inv = (mask[2*idx] != 0) || (mask[2*idx+1] != 0) || (n >= ncount[b]);
        g_inv[idx] = inv ? 1 : 0;
        const unsigned bal = __ballot_sync(0xffffffffu, inv);
        if ((threadIdx.x & 31) == 0) g_invbits[idx >> 5] = bal;
    }
}

// h (f32) -> g_hh (fp16); one float4 per thread
__global__ void convh_kernel(const float* __restrict__ h) {
    const int idx = blockIdx.x * 256 + threadIdx.x;   // 0 .. M_*D_/4-1
    const float4 v = *(const float4*)&h[idx * 4];
    uint2 o;
    o.x = pack_h2(v.x, v.y);
    o.y = pack_h2(v.z, v.w);
    *(uint2*)&g_hh[idx * 4] = o;
}

// W (f32 [k][n]) -> g_wt (fp16 W^T [n][k]); 4 k-entries per thread
__global__ void convw_kernel(const float* __restrict__ Wq, const float* __restrict__ Wk,
                             const float* __restrict__ Wv, const float* __restrict__ Wo) {
    const int idx = blockIdx.x * 256 + threadIdx.x;   // 65536 threads
    const int m = idx >> 14;                          // matrix 0..3
    const int r = idx & 16383;
    const int n = r & 255;
    const int k0 = (r >> 8) * 4;
    const float* src = (m == 0) ? Wq : (m == 1) ? Wk : (m == 2) ? Wv : Wo;
    uint2 o;
    o.x = pack_h2(src[(k0+0)*D_ + n], src[(k0+1)*D_ + n]);
    o.y = pack_h2(src[(k0+2)*D_ + n], src[(k0+3)*D_ + n]);
    *(uint2*)&g_wt[m*D_*D_ + n*D_ + k0] = o;
}

// ---------------- fp16 mma GEMM: C[Mx256] = A[Mx256] @ W[256x256] (+bias[,res])
// block 128x128, BK=32, 256 threads / 8 warps, warp tile 32x64.
// A smem [m][k] stride 40h; B smem = W^T rows [n][k] stride 40h (both the
// validated non-trans ldmatrix pattern from attn phase 1). 3-stage cp.async.
// OUT: 0 = f32 + bias + res (oproj), 2 = fp16 (acc+bias)*scale (Q/K/V)
#define HSTAGE_B 20480            // bytes per stage: (128*40 + 128*40) halves
#define GEMMH_SMEM_BYTES (3*HSTAGE_B)   // 61440

template<int OUT>
__device__ __forceinline__ void gemm_h(const __half* __restrict__ A,
                                       const __half* __restrict__ Wt,
                                       const float* __restrict__ bias,
                                       const float* __restrict__ res,
                                       float* __restrict__ Cf,
                                       __half* __restrict__ Ch,
                                       float scale) {
    extern __shared__ char smc[];
    const uint32_t sb = (uint32_t)__cvta_generic_to_shared(smc);

    const int tid  = threadIdx.x;
    const int lane = tid & 31, warp = tid >> 5;
    const int g = lane >> 2, t = lane & 3;
    const int lrow = lane & 7, grp = lane >> 3;
    const int mw = (warp >> 1) * 32, nw = (warp & 1) * 64;
    const int row0 = blockIdx.x * 128, col0 = blockIdx.y * 128;

    const int ar = tid >> 2, ac = (tid & 3) * 8;    // loader: 64 rows x 32h, 2 passes

    float acc[2][8][4];
#pragma unroll
    for (int i = 0; i < 2; i++)
#pragma unroll
        for (int j = 0; j < 8; j++)
#pragma unroll
            for (int q = 0; q < 4; q++) acc[i][j][q] = 0.f;

    const __half* gA = A  + (size_t)(row0 + ar)*D_ + ac;
    const __half* gB = Wt + (size_t)(col0 + ar)*D_ + ac;

    auto issue = [&](int chunk, int stage) {
        __half* As = (__half*)(smc + stage*HSTAGE_B);
        __half* Bs = As + 5120;
#pragma unroll
        for (int p = 0; p < 2; p++) {
            cpasync16(&As[(ar + 64*p)*40 + ac], gA + (size_t)(64*p)*D_ + chunk*32);
            cpasync16(&Bs[(ar + 64*p)*40 + ac], gB + (size_t)(64*p)*D_ + chunk*32);
        }
        asm volatile("cp.async.commit_group;\n" ::: "memory");
    };

    issue(0, 0);
    issue(1, 1);

    // ldmatrix bases (byte offsets): A rows on (grp&1)*8, k on (grp>>1)*8;
    // B (=W^T) rows(n) on (grp>>1)*8, k on (grp&1)*8  [attn phase-1 pattern]
    const uint32_t a_base = sb
        + (uint32_t)(((mw + (grp&1)*8 + lrow)*40 + (grp>>1)*8) * 2);
    const uint32_t b_base = sb + 10240
        + (uint32_t)(((nw + (grp>>1)*8 + lrow)*40 + (grp&1)*8) * 2);

    for (int i = 0; i < 8; i++) {
        if (i < 7) asm volatile("cp.async.wait_group 1;\n" ::: "memory");
        else       asm volatile("cp.async.wait_group 0;\n" ::: "memory");
        __syncthreads();
        if (i < 6) issue(i + 2, (i + 2) % 3);

        const uint32_t st = (uint32_t)((i % 3) * HSTAGE_B);
#pragma unroll
        for (int kh = 0; kh < 2; kh++) {
            uint32_t aq[2][4];
            ldsm_x4(aq[0][0], aq[0][1], aq[0][2], aq[0][3],
                    a_base + st + kh*32);
            ldsm_x4(aq[1][0], aq[1][1], aq[1][2], aq[1][3],
                    a_base + st + 1280 + kh*32);          // +16 rows * 80B
#pragma unroll
            for (int nb = 0; nb < 4; nb++) {
                uint32_t bf[4];
                ldsm_x4(bf[0], bf[1], bf[2], bf[3],
                        b_base + st + nb*1280 + kh*32);
                mma_f16(acc[0][nb*2+0], aq[0], bf);
                mma_f16(acc[0][nb*2+1], aq[0], bf + 2);
                mma_f16(acc[1][nb*2+0], aq[1], bf);
                mma_f16(acc[1][nb*2+1], aq[1], bf + 2);
            }
        }
        __syncthreads();
    }

#pragma unroll
    for (int ma = 0; ma < 2; ma++) {
        const int r0g = row0 + mw + ma*16 + g;
#pragma unroll
        for (int na = 0; na < 8; na++) {
            const int c0 = col0 + nw + na*8 + 2*t;
            float2 o0, o1;
            o0.x = acc[ma][na][0] + bias[c0];
            o0.y = acc[ma][na][1] + bias[c0+1];
            o1.x = acc[ma][na][2] + bias[c0];
            o1.y = acc[ma][na][3] + bias[c0+1];
            if (OUT == 2) {
                *(uint32_t*)&Ch[(size_t)r0g*D_ + c0]     = pack_h2(o0.x*scale, o0.y*scale);
                *(uint32_t*)&Ch[(size_t)(r0g+8)*D_ + c0] = pack_h2(o1.x*scale, o1.y*scale);
            } else {
                const float2 ra = *(const float2*)&res[(size_t)r0g*D_ + c0];
                const float2 rb = *(const float2*)&res[(size_t)(r0g+8)*D_ + c0];
                o0.x += ra.x; o0.y += ra.y;
                o1.x += rb.x; o1.y += rb.y;
                *(float2*)&Cf[(size_t)r0g*D_ + c0]     = o0;
                *(float2*)&Cf[(size_t)(r0g+8)*D_ + c0] = o1;
            }
        }
    }
}

__global__ void __launch_bounds__(256)
qkv_kernel(const float* __restrict__ bq, const float* __restrict__ bk,
           const float* __restrict__ bv) {
    const int z = blockIdx.z;   // 0=Q, 1=K, 2=V
    const float* bb = (z == 0) ? bq : (z == 1) ? bk : bv;
    __half* out    = (z == 0) ? g_qh : (z == 1) ? g_kh : g_vh;
    gemm_h<2>(g_hh, g_wt + z*D_*D_, bb, nullptr, nullptr, out,
              (z == 0) ? QSCALE : 1.0f);
}

__global__ void __launch_bounds__(256)
oproj_kernel(const float* __restrict__ bo,
             const float* __restrict__ hres, float* __restrict__ out) {
    gemm_h<0>(g_aoh, g_wt + 3*D_*D_, bo, hres, out, nullptr, 1.0f);
}

// ---------------- register-flash attention (fp16 QK + fp16 PV, R11-validated)
// 512 thr / 16 warps; warp = (ma 0..3) x (kspl 0..3): 16 q-rows x 128 keys.
#define KH_STR  40                // halves per K/Q smem row (80 B, cf-free ldsm)
#define VT_STR  520               // halves per dk row of V^T
#define OFFB_K  0                 // Kh[512][40]h  = 40960 B
#define OFFB_VT 40960             // Vt[32][520]h  = 33280 B
#define OFFB_Q  74240             // Qh[64][40]h   = 5120 B
#define OFFB_OP 79360             // Op[16][16][40]f = 40960 B
#define OFFB_MR 120320            // Mred[64][4]f
#define OFFB_SR 121344            // Sred[64][4]f
#define ATTN_SMEM_BYTES 122368

__global__ void __launch_bounds__(512)
attn_kernel() {
    extern __shared__ char smc[];
    __half* Khs  = (__half*)(smc + OFFB_K);
    __half* Vth  = (__half*)(smc + OFFB_VT);
    __half* Qhs  = (__half*)(smc + OFFB_Q);
    float*  Op   = (float*) (smc + OFFB_OP);
    float*  Mred = (float*) (smc + OFFB_MR);
    float*  Sred = (float*) (smc + OFFB_SR);
    const uint32_t sb = (uint32_t)__cvta_generic_to_shared(smc);

    const int tid  = threadIdx.x;
    const int lane = tid & 31;
    const int warp = tid >> 5;
    const int g = lane >> 2, t = lane & 3;
    const int lrow = lane & 7, grp = lane >> 3;
    const int ma   = warp >> 2;          // q-row atom 0..3
    const int kspl = warp & 3;           // key-split 0..3
    const int bh   = blockIdx.x >> 1;
    const int half = blockIdx.x & 1;
    const int b  = bh >> 3;
    const int hh = bh & 7;

    const __half* Qg  = g_qh  + (size_t)b*N_*D_ + hh*DK_;
    const __half* Kg  = g_kh  + (size_t)b*N_*D_ + hh*DK_;
    const __half* Vg  = g_vh  + (size_t)b*N_*D_ + hh*DK_;
    __half*       Ogh = g_aoh + (size_t)b*N_*D_ + hh*DK_;

    // key-invalid bitmask for this warp's 128 keys; pre-shift per thread
    uint32_t invw[4];
#pragma unroll
    for (int j = 0; j < 4; j++)
        invw[j] = g_invbits[b*16 + kspl*4 + j] >> (t << 1);

    // ---- load K (fp16 row-major, stride 40h) and V (fp16 transposed) ----
    {
        const int r = tid >> 3, cg = (tid & 7) * 4;     // 4 halves per thread
#pragma unroll
        for (int p = 0; p < 8; p++) {
            const int key = r + 64*p;
            *(uint2*)&Khs[key*KH_STR + cg] = *(const uint2*)&Kg[(size_t)key*D_ + cg];
            const uint2 u = *(const uint2*)&Vg[(size_t)key*D_ + cg];
            const __half2 v01 = *reinterpret_cast<const __half2*>(&u.x);
            const __half2 v23 = *reinterpret_cast<const __half2*>(&u.y);
            Vth[(cg+0)*VT_STR + key] = __low2half(v01);
            Vth[(cg+1)*VT_STR + key] = __high2half(v01);
            Vth[(cg+2)*VT_STR + key] = __low2half(v23);
            Vth[(cg+3)*VT_STR + key] = __high2half(v23);
        }
    }

    const int kb0 = kspl * 128;
    const int rr0 = ma*16 + g;                   // row within 64-row tile
    const uint32_t FULL = 0xffffffffu;

    // ldmatrix base addresses (byte offsets in smem), NON-trans:
    const uint32_t qa_base = sb + OFFB_Q
        + (uint32_t)(((ma*16 + (grp&1)*8 + lrow)*KH_STR + (grp>>1)*8) * 2);
    const uint32_t ka_row  = (uint32_t)((grp>>1)*8 + lrow);
    const uint32_t ka_koff = (uint32_t)((grp&1)*8);

    for (int qt = 0; qt < 4; qt++) {
        const int q0 = half*256 + qt*64;

        // ---- stage Q tile 64x32 fp16 ----
        __syncthreads();     // Op/Qhs free (also covers initial K/V load at qt=0)
        {
            const int r = tid >> 3, cg = (tid & 7) * 4;
            *(uint2*)&Qhs[r*KH_STR + cg] = *(const uint2*)&Qg[(size_t)(q0 + r)*D_ + cg];
        }
        __syncthreads();

        const bool iq0 = g_inv[b*N_ + q0 + rr0]     != 0;
        const bool iq1 = g_inv[b*N_ + q0 + rr0 + 8] != 0;

        // ---- phase 1: S[16 x 128] = Q @ K^T, fp16 m16n8k16 ----
        uint32_t aq[2][4];
        ldsm_x4(aq[0][0], aq[0][1], aq[0][2], aq[0][3], qa_base);
        ldsm_x4(aq[1][0], aq[1][1], aq[1][2], aq[1][3], qa_base + 32);

        float acc[16][4];
#pragma unroll
        for (int j = 0; j < 8; j++) {
            const uint32_t kaddr = sb + OFFB_K
                + (uint32_t)((((kb0 + j*16) + ka_row)*KH_STR + ka_koff) * 2);
            uint32_t kb[4], kc[4];
            ldsm_x4(kb[0], kb[1], kb[2], kb[3], kaddr);        // dk 0-15
            ldsm_x4(kc[0], kc[1], kc[2], kc[3], kaddr + 32);   // dk 16-31
            acc[2*j][0] = acc[2*j][1] = acc[2*j][2] = acc[2*j][3] = 0.f;
            acc[2*j+1][0] = acc[2*j+1][1] = acc[2*j+1][2] = acc[2*j+1][3] = 0.f;
            mma_f16(acc[2*j],   aq[0], kb);
            mma_f16(acc[2*j],   aq[1], kc);
            mma_f16(acc[2*j+1], aq[0], kb + 2);
            mma_f16(acc[2*j+1], aq[1], kc + 2);
        }

        // ---- mask (regs), per-warp row max ----
        float mx0 = -1e30f, mx1 = -1e30f;
#pragma unroll
        for (int na = 0; na < 16; na++) {
            const uint32_t w = invw[na >> 2] >> ((na & 3) << 3);
            const bool ik0 = (w & 1u) != 0;
            const bool ik1 = (w & 2u) != 0;
            acc[na][0] = (iq0 || ik0) ? -1e9f : acc[na][0];
            acc[na][1] = (iq0 || ik1) ? -1e9f : acc[na][1];
            acc[na][2] = (iq1 || ik0) ? -1e9f : acc[na][2];
            acc[na][3] = (iq1 || ik1) ? -1e9f : acc[na][3];
            mx0 = fmaxf(mx0, fmaxf(acc[na][0], acc[na][1]));
            mx1 = fmaxf(mx1, fmaxf(acc[na][2], acc[na][3]));
        }
        mx0 = fmaxf(mx0, __shfl_xor_sync(FULL, mx0, 1));
        mx0 = fmaxf(mx0, __shfl_xor_sync(FULL, mx0, 2));
        mx1 = fmaxf(mx1, __shfl_xor_sync(FULL, mx1, 1));
        mx1 = fmaxf(mx1, __shfl_xor_sync(FULL, mx1, 2));
        if (t == 0) {
            Mred[rr0*4 + kspl]     = mx0;
            Mred[(rr0+8)*4 + kspl] = mx1;
        }
        __syncthreads();

        const float4 m4a = *(float4*)&Mred[rr0*4];
        const float4 m4b = *(float4*)&Mred[(rr0+8)*4];
        const float M0 = fmaxf(fmaxf(m4a.x, m4a.y), fmaxf(m4a.z, m4a.w));
        const float M1 = fmaxf(fmaxf(m4b.x, m4b.y), fmaxf(m4b.z, m4b.w));

        // ---- exp2 + row sum (regs), pack P to fp16 A-fragments ----
        uint32_t ph[16][2];
        float sm0 = 0.f, sm1 = 0.f;
#pragma unroll
        for (int na = 0; na < 16; na++) {
            const float e0 = ex2f(acc[na][0] - M0);
            const float e1 = ex2f(acc[na][1] - M0);
            const float e2 = ex2f(acc[na][2] - M1);
            const float e3 = ex2f(acc[na][3] - M1);
            sm0 += e0 + e1;
            sm1 += e2 + e3;
            ph[na][0] = pack_h2(e0, e1);
            ph[na][1] = pack_h2(e2, e3);
        }
        sm0 += __shfl_xor_sync(FULL, sm0, 1);
        sm0 += __shfl_xor_sync(FULL, sm0, 2);
        sm1 += __shfl_xor_sync(FULL, sm1, 1);
        sm1 += __shfl_xor_sync(FULL, sm1, 2);
        if (t == 0) {
            Sred[rr0*4 + kspl]     = sm0;
            Sred[(rr0+8)*4 + kspl] = sm1;
        }

        // ---- phase 3: O_partial[16 x 32] = P @ V, fp16 m16n8k16 ----
        float oacc[4][4];
#pragma unroll
        for (int na = 0; na < 4; na++)
#pragma unroll
            for (int q = 0; q < 4; q++) oacc[na][q] = 0.f;

#pragma unroll
        for (int j = 0; j < 8; j++) {
            const uint32_t pa[4] = { ph[2*j][0], ph[2*j][1], ph[2*j+1][0], ph[2*j+1][1] };
            const int kk = kb0 + 16*j + 2*t;
#pragma unroll
            for (int na = 0; na < 4; na++) {
                const __half* bb = Vth + (na*8 + g)*VT_STR + kk;
                uint32_t bf[2] = { *(const uint32_t*)bb, *(const uint32_t*)(bb + 8) };
                mma_f16(oacc[na], pa, bf);
            }
        }

        // ---- store partials ----
        {
            float* op = Op + warp * 640;
#pragma unroll
            for (int na = 0; na < 4; na++) {
                const int c = na*8 + 2*t;
                *(float2*)&op[g*40 + c]     = make_float2(oacc[na][0], oacc[na][1]);
                *(float2*)&op[(g+8)*40 + c] = make_float2(oacc[na][2], oacc[na][3]);
            }
        }
        __syncthreads();

        // ---- combine 4 key-split partials, normalize, store fp16 ----
        {
            const int r  = tid >> 3;            // 0..63
            const int c4 = (tid & 7) * 4;       // 0..28
            const int wb = (r >> 4) * 4;        // ma*4
            const int rl = r & 15;
            float4 o = {0.f, 0.f, 0.f, 0.f};
#pragma unroll
            for (int kk = 0; kk < 4; kk++) {
                const float4 p = *(float4*)&Op[(wb + kk)*640 + rl*40 + c4];
                o.x += p.x; o.y += p.y; o.z += p.z; o.w += p.w;
            }
            const float4 s4 = *(float4*)&Sred[r*4];
            const float rs = 1.0f / (s4.x + s4.y + s4.z + s4.w);
            uint2 ov;
            ov.x = pack_h2(o.x*rs, o.y*rs);
            ov.y = pack_h2(o.z*rs, o.w*rs);
            *(uint2*)&Ogh[(size_t)(q0 + r)*D_ + c4] = ov;
        }
    }
}

// ---------------- launcher --------------------------------------------------
extern "C" void kernel_launch(void* const* d_in, const int* in_sizes, int n_in,
                              void* d_out, int out_size) {
    const float* h    = (const float*)d_in[0];
    const int*   mask = (const int*)  d_in[1];
    const int*   nc   = (const int*)  d_in[2];
    const float* Wq   = (const float*)d_in[3];
    const float* bq   = (const float*)d_in[4];
    const float* Wk   = (const float*)d_in[5];
    const float* bk   = (const float*)d_in[6];
    const float* Wv   = (const float*)d_in[7];
    const float* bv   = (const float*)d_in[8];
    const float* Wo   = (const float*)d_in[9];
    const float* bo   = (const float*)d_in[10];
    float* out = (float*)d_out;

    cudaFuncSetAttribute(attn_kernel, cudaFuncAttributeMaxDynamicSharedMemorySize,
                         ATTN_SMEM_BYTES);
    cudaFuncSetAttribute(qkv_kernel, cudaFuncAttributeMaxDynamicSharedMemorySize,
                         GEMMH_SMEM_BYTES);
    cudaFuncSetAttribute(oproj_kernel, cudaFuncAttributeMaxDynamicSharedMemorySize,
                         GEMMH_SMEM_BYTES);

    mask_kernel<<<M_/256, 256>>>(mask, nc);
    convh_kernel<<<M_*D_/1024, 256>>>(h);
    convw_kernel<<<256, 256>>>(Wq, Wk, Wv, Wo);
    qkv_kernel<<<dim3(M_/128, D_/128, 3), 256, GEMMH_SMEM_BYTES>>>(bq, bk, bv);
    attn_kernel<<<B_*H_*2, 512, ATTN_SMEM_BYTES>>>();
    oproj_kernel<<<dim3(M_/128, D_/128), 256, GEMMH_SMEM_BYTES>>>(bo, h, out);
}

// round 14
// speedup vs baseline: 5.3879x; 1.1154x over previous
#include <cuda_runtime.h>
#include <cuda_fp16.h>
#include <math.h>
#include <stdint.h>

#define B_  64
#define N_  512
#define D_  256
#define H_  8
#define DK_ 32
#define M_  (B_*N_)   // 32768

// Q pre-scale: (1/sqrt(DK)) * log2(e)  -> softmax done in exp2 domain
#define QSCALE 0.25502421277695494f

// ---------------- scratch (static device globals; no allocation) ----------
__device__ __align__(256) __half g_hh[M_*D_];     // h in fp16
__device__ __align__(256) __half g_qh[M_*D_];
__device__ __align__(256) __half g_kh[M_*D_];
__device__ __align__(256) __half g_vh[M_*D_];
__device__ __align__(256) __half g_aoh[M_*D_];    // attention output fp16
__device__ __align__(256) __half g_wt[4*D_*D_];   // fp16 W^T (n-major) x4
__device__ unsigned char g_inv[M_];
__device__ unsigned int  g_invbits[M_/32];

// ---------------- helpers ---------------------------------------------------
__device__ __forceinline__ uint32_t pack_h2(float lo, float hi) {
    uint32_t r;
    asm("cvt.rn.f16x2.f32 %0, %1, %2;" : "=r"(r) : "f"(hi), "f"(lo));
    return r;
}
__device__ __forceinline__ float ex2f(float x) {
    float r;
    asm("ex2.approx.f32 %0, %1;" : "=f"(r) : "f"(x));
    return r;
}
__device__ __forceinline__ uint32_t h2exp2(uint32_t x) {
    uint32_t r;
    asm("ex2.approx.f16x2 %0, %1;" : "=r"(r) : "r"(x));
    return r;
}
__device__ __forceinline__ void mma_f16(float* d, const uint32_t* a, const uint32_t* b) {
    asm volatile(
        "mma.sync.aligned.m16n8k16.row.col.f32.f16.f16.f32 "
        "{%0,%1,%2,%3}, {%4,%5,%6,%7}, {%8,%9}, {%0,%1,%2,%3};\n"
        : "+f"(d[0]), "+f"(d[1]), "+f"(d[2]), "+f"(d[3])
        : "r"(a[0]), "r"(a[1]), "r"(a[2]), "r"(a[3]), "r"(b[0]), "r"(b[1]));
}
__device__ __forceinline__ void ldsm_x4(uint32_t& r0, uint32_t& r1, uint32_t& r2,
                                        uint32_t& r3, uint32_t saddr) {
    asm volatile("ldmatrix.sync.aligned.m8n8.x4.shared.b16 {%0,%1,%2,%3}, [%4];"
                 : "=r"(r0), "=r"(r1), "=r"(r2), "=r"(r3) : "r"(saddr));
}
__device__ __forceinline__ void cpasync16(void* smem_dst, const void* gptr) {
    uint32_t d = (uint32_t)__cvta_generic_to_shared(smem_dst);
    asm volatile("cp.async.ca.shared.global [%0], [%1], 16;\n" :: "r"(d), "l"(gptr));
}

// ---------------- prep kernels ----------------------------------------------
__global__ void mask_kernel(const int* __restrict__ mask,
                            const int* __restrict__ ncount) {
    const int idx = blockIdx.x * 256 + threadIdx.x;
    if (idx < M_) {
        const int b = idx >> 9;
        const int n = idx & 511;
        const bool inv = (mask[2*idx] != 0) || (mask[2*idx+1] != 0) || (n >= ncount[b]);
        g_inv[idx] = inv ? 1 : 0;
        const unsigned bal = __ballot_sync(0xffffffffu, inv);
        if ((threadIdx.x & 31) == 0) g_invbits[idx >> 5] = bal;
    }
}

// h (f32) -> g_hh (fp16); one float4 per thread
__global__ void convh_kernel(const float* __restrict__ h) {
    const int idx = blockIdx.x * 256 + threadIdx.x;   // 0 .. M_*D_/4-1
    const float4 v = *(const float4*)&h[idx * 4];
    uint2 o;
    o.x = pack_h2(v.x, v.y);
    o.y = pack_h2(v.z, v.w);
    *(uint2*)&g_hh[idx * 4] = o;
}

// W (f32 [k][n]) -> g_wt (fp16 W^T [n][k]); 4 k-entries per thread
__global__ void convw_kernel(const float* __restrict__ Wq, const float* __restrict__ Wk,
                             const float* __restrict__ Wv, const float* __restrict__ Wo) {
    const int idx = blockIdx.x * 256 + threadIdx.x;   // 65536 threads
    const int m = idx >> 14;                          // matrix 0..3
    const int r = idx & 16383;
    const int n = r & 255;
    const int k0 = (r >> 8) * 4;
    const float* src = (m == 0) ? Wq : (m == 1) ? Wk : (m == 2) ? Wv : Wo;
    uint2 o;
    o.x = pack_h2(src[(k0+0)*D_ + n], src[(k0+1)*D_ + n]);
    o.y = pack_h2(src[(k0+2)*D_ + n], src[(k0+3)*D_ + n]);
    *(uint2*)&g_wt[m*D_*D_ + n*D_ + k0] = o;
}

// ---------------- fp16 mma GEMM (validated R12) ------------------------------
// block 128x128, BK=32, 256 threads / 8 warps, warp tile 32x64.
// OUT: 0 = f32 + bias + res (oproj), 2 = fp16 (acc+bias)*scale (Q/K/V)
#define HSTAGE_B 20480            // bytes per stage: (128*40 + 128*40) halves
#define GEMMH_SMEM_BYTES (3*HSTAGE_B)   // 61440

template<int OUT>
__device__ __forceinline__ void gemm_h(const __half* __restrict__ A,
                                       const __half* __restrict__ Wt,
                                       const float* __restrict__ bias,
                                       const float* __restrict__ res,
                                       float* __restrict__ Cf,
                                       __half* __restrict__ Ch,
                                       float scale) {
    extern __shared__ char smc[];
    const uint32_t sb = (uint32_t)__cvta_generic_to_shared(smc);

    const int tid  = threadIdx.x;
    const int lane = tid & 31, warp = tid >> 5;
    const int g = lane >> 2, t = lane & 3;
    const int lrow = lane & 7, grp = lane >> 3;
    const int mw = (warp >> 1) * 32, nw = (warp & 1) * 64;
    const int row0 = blockIdx.x * 128, col0 = blockIdx.y * 128;

    const int ar = tid >> 2, ac = (tid & 3) * 8;    // loader: 64 rows x 32h, 2 passes

    float acc[2][8][4];
#pragma unroll
    for (int i = 0; i < 2; i++)
#pragma unroll
        for (int j = 0; j < 8; j++)
#pragma unroll
            for (int q = 0; q < 4; q++) acc[i][j][q] = 0.f;

    const __half* gA = A  + (size_t)(row0 + ar)*D_ + ac;
    const __half* gB = Wt + (size_t)(col0 + ar)*D_ + ac;

    auto issue = [&](int chunk, int stage) {
        __half* As = (__half*)(smc + stage*HSTAGE_B);
        __half* Bs = As + 5120;
#pragma unroll
        for (int p = 0; p < 2; p++) {
            cpasync16(&As[(ar + 64*p)*40 + ac], gA + (size_t)(64*p)*D_ + chunk*32);
            cpasync16(&Bs[(ar + 64*p)*40 + ac], gB + (size_t)(64*p)*D_ + chunk*32);
        }
        asm volatile("cp.async.commit_group;\n" ::: "memory");
    };

    issue(0, 0);
    issue(1, 1);

    const uint32_t a_base = sb
        + (uint32_t)(((mw + (grp&1)*8 + lrow)*40 + (grp>>1)*8) * 2);
    const uint32_t b_base = sb + 10240
        + (uint32_t)(((nw + (grp>>1)*8 + lrow)*40 + (grp&1)*8) * 2);

    for (int i = 0; i < 8; i++) {
        if (i < 7) asm volatile("cp.async.wait_group 1;\n" ::: "memory");
        else       asm volatile("cp.async.wait_group 0;\n" ::: "memory");
        __syncthreads();
        if (i < 6) issue(i + 2, (i + 2) % 3);

        const uint32_t st = (uint32_t)((i % 3) * HSTAGE_B);
#pragma unroll
        for (int kh = 0; kh < 2; kh++) {
            uint32_t aq[2][4];
            ldsm_x4(aq[0][0], aq[0][1], aq[0][2], aq[0][3],
                    a_base + st + kh*32);
            ldsm_x4(aq[1][0], aq[1][1], aq[1][2], aq[1][3],
                    a_base + st + 1280 + kh*32);          // +16 rows * 80B
#pragma unroll
            for (int nb = 0; nb < 4; nb++) {
                uint32_t bf[4];
                ldsm_x4(bf[0], bf[1], bf[2], bf[3],
                        b_base + st + nb*1280 + kh*32);
                mma_f16(acc[0][nb*2+0], aq[0], bf);
                mma_f16(acc[0][nb*2+1], aq[0], bf + 2);
                mma_f16(acc[1][nb*2+0], aq[1], bf);
                mma_f16(acc[1][nb*2+1], aq[1], bf + 2);
            }
        }
        __syncthreads();
    }

#pragma unroll
    for (int ma = 0; ma < 2; ma++) {
        const int r0g = row0 + mw + ma*16 + g;
#pragma unroll
        for (int na = 0; na < 8; na++) {
            const int c0 = col0 + nw + na*8 + 2*t;
            float2 o0, o1;
            o0.x = acc[ma][na][0] + bias[c0];
            o0.y = acc[ma][na][1] + bias[c0+1];
            o1.x = acc[ma][na][2] + bias[c0];
            o1.y = acc[ma][na][3] + bias[c0+1];
            if (OUT == 2) {
                *(uint32_t*)&Ch[(size_t)r0g*D_ + c0]     = pack_h2(o0.x*scale, o0.y*scale);
                *(uint32_t*)&Ch[(size_t)(r0g+8)*D_ + c0] = pack_h2(o1.x*scale, o1.y*scale);
            } else {
                const float2 ra = *(const float2*)&res[(size_t)r0g*D_ + c0];
                const float2 rb = *(const float2*)&res[(size_t)(r0g+8)*D_ + c0];
                o0.x += ra.x; o0.y += ra.y;
                o1.x += rb.x; o1.y += rb.y;
                *(float2*)&Cf[(size_t)r0g*D_ + c0]     = o0;
                *(float2*)&Cf[(size_t)(r0g+8)*D_ + c0] = o1;
            }
        }
    }
}

__global__ void __launch_bounds__(256)
qkv_kernel(const float* __restrict__ bq, const float* __restrict__ bk,
           const float* __restrict__ bv) {
    const int z = blockIdx.z;   // 0=Q, 1=K, 2=V
    const float* bb = (z == 0) ? bq : (z == 1) ? bk : bv;
    __half* outp   = (z == 0) ? g_qh : (z == 1) ? g_kh : g_vh;
    gemm_h<2>(g_hh, g_wt + z*D_*D_, bb, nullptr, nullptr, outp,
              (z == 0) ? QSCALE : 1.0f);
}

__global__ void __launch_bounds__(256)
oproj_kernel(const float* __restrict__ bo,
             const float* __restrict__ hres, float* __restrict__ out) {
    gemm_h<0>(g_aoh, g_wt + 3*D_*D_, bo, hres, out, nullptr, 1.0f);
}

// ---------------- register-flash attention ----------------------------------
// R12 base + this round: per-warp max (deferred rescale at combine),
// exp via ex2.approx.f16x2, row sums via ones-column mma. 3 barriers/tile.
#define KH_STR  40                // halves per K/Q smem row (80 B, cf-free ldsm)
#define VT_STR  520               // halves per dk row of V^T
#define OFFB_K  0                 // Kh[512][40]h  = 40960 B
#define OFFB_VT 40960             // Vt[32][520]h  = 33280 B
#define OFFB_Q  74240             // Qh[64][40]h   = 5120 B
#define OFFB_OP 79360             // Op[16][16][40]f = 40960 B
#define OFFB_MR 120320            // Mred[64][4]f (per-warp maxes)
#define OFFB_SR 121344            // Sred[64][4]f (per-warp sums)
#define ATTN_SMEM_BYTES 122368

__global__ void __launch_bounds__(512)
attn_kernel() {
    extern __shared__ char smc[];
    __half* Qhs  = (__half*)(smc + OFFB_Q);
    __half* Khs  = (__half*)(smc + OFFB_K);
    __half* Vth  = (__half*)(smc + OFFB_VT);
    float*  Op   = (float*) (smc + OFFB_OP);
    float*  Mred = (float*) (smc + OFFB_MR);
    float*  Sred = (float*) (smc + OFFB_SR);
    const uint32_t sb = (uint32_t)__cvta_generic_to_shared(smc);

    const int tid  = threadIdx.x;
    const int lane = tid & 31;
    const int warp = tid >> 5;
    const int g = lane >> 2, t = lane & 3;
    const int lrow = lane & 7, grp = lane >> 3;
    const int ma   = warp >> 2;          // q-row atom 0..3
    const int kspl = warp & 3;           // key-split 0..3
    const int bh   = blockIdx.x >> 1;
    const int half = blockIdx.x & 1;
    const int b  = bh >> 3;
    const int hh = bh & 7;

    const __half* Qg  = g_qh  + (size_t)b*N_*D_ + hh*DK_;
    const __half* Kg  = g_kh  + (size_t)b*N_*D_ + hh*DK_;
    const __half* Vg  = g_vh  + (size_t)b*N_*D_ + hh*DK_;
    __half*       Ogh = g_aoh + (size_t)b*N_*D_ + hh*DK_;

    uint32_t invw[4];
#pragma unroll
    for (int j = 0; j < 4; j++)
        invw[j] = g_invbits[b*16 + kspl*4 + j] >> (t << 1);

    // ---- load K (fp16 row-major) and V (fp16 transposed) ----
    {
        const int r = tid >> 3, cg = (tid & 7) * 4;     // 4 halves per thread
#pragma unroll
        for (int p = 0; p < 8; p++) {
            const int key = r + 64*p;
            *(uint2*)&Khs[key*KH_STR + cg] = *(const uint2*)&Kg[(size_t)key*D_ + cg];
            const uint2 u = *(const uint2*)&Vg[(size_t)key*D_ + cg];
            const __half2 v01 = *reinterpret_cast<const __half2*>(&u.x);
            const __half2 v23 = *reinterpret_cast<const __half2*>(&u.y);
            Vth[(cg+0)*VT_STR + key] = __low2half(v01);
            Vth[(cg+1)*VT_STR + key] = __high2half(v01);
            Vth[(cg+2)*VT_STR + key] = __low2half(v23);
            Vth[(cg+3)*VT_STR + key] = __high2half(v23);
        }
    }

    const int kb0 = kspl * 128;
    const int rr0 = ma*16 + g;                   // row within 64-row tile
    const int rr04 = rr0 * 4;
    const uint32_t FULL = 0xffffffffu;
    // ones-column B-frag for row-sum mma: col 0 = 1.0, cols 1..7 = 0
    const uint32_t onesf = (g == 0) ? 0x3C003C00u : 0u;
    const uint32_t onesbf[2] = { onesf, onesf };

    const uint32_t qa_base = sb + OFFB_Q
        + (uint32_t)(((ma*16 + (grp&1)*8 + lrow)*KH_STR + (grp>>1)*8) * 2);
    const uint32_t ka_row  = (uint32_t)((grp>>1)*8 + lrow);
    const uint32_t ka_koff = (uint32_t)((grp&1)*8);

    for (int qt = 0; qt < 4; qt++) {
        const int q0 = half*256 + qt*64;

        // ---- stage Q tile 64x32 fp16 ----
        __syncthreads();     // prior combine done; Qs/Op/Mred/Sred free
        {
            const int r = tid >> 3, cg = (tid & 7) * 4;
            *(uint2*)&Qhs[r*KH_STR + cg] = *(const uint2*)&Qg[(size_t)(q0 + r)*D_ + cg];
        }
        __syncthreads();

        const bool iq0 = g_inv[b*N_ + q0 + rr0]     != 0;
        const bool iq1 = g_inv[b*N_ + q0 + rr0 + 8] != 0;

        // ---- phase 1: S[16 x 128] = Q @ K^T, fp16 m16n8k16 ----
        uint32_t aq[2][4];
        ldsm_x4(aq[0][0], aq[0][1], aq[0][2], aq[0][3], qa_base);
        ldsm_x4(aq[1][0], aq[1][1], aq[1][2], aq[1][3], qa_base + 32);

        float acc[16][4];
#pragma unroll
        for (int j = 0; j < 8; j++) {
            const uint32_t kaddr = sb + OFFB_K
                + (uint32_t)((((kb0 + j*16) + ka_row)*KH_STR + ka_koff) * 2);
            uint32_t kb[4], kc[4];
            ldsm_x4(kb[0], kb[1], kb[2], kb[3], kaddr);        // dk 0-15
            ldsm_x4(kc[0], kc[1], kc[2], kc[3], kaddr + 32);   // dk 16-31
            acc[2*j][0] = acc[2*j][1] = acc[2*j][2] = acc[2*j][3] = 0.f;
            acc[2*j+1][0] = acc[2*j+1][1] = acc[2*j+1][2] = acc[2*j+1][3] = 0.f;
            mma_f16(acc[2*j],   aq[0], kb);
            mma_f16(acc[2*j],   aq[1], kc);
            mma_f16(acc[2*j+1], aq[0], kb + 2);
            mma_f16(acc[2*j+1], aq[1], kc + 2);
        }

        // ---- mask (regs), per-warp row max (quad shuffles only) ----
        float mx0 = -1e30f, mx1 = -1e30f;
#pragma unroll
        for (int na = 0; na < 16; na++) {
            const uint32_t w = invw[na >> 2] >> ((na & 3) << 3);
            const bool ik0 = (w & 1u) != 0;
            const bool ik1 = (w & 2u) != 0;
            acc[na][0] = (iq0 || ik0) ? -1e9f : acc[na][0];
            acc[na][1] = (iq0 || ik1) ? -1e9f : acc[na][1];
            acc[na][2] = (iq1 || ik0) ? -1e9f : acc[na][2];
            acc[na][3] = (iq1 || ik1) ? -1e9f : acc[na][3];
            mx0 = fmaxf(mx0, fmaxf(acc[na][0], acc[na][1]));
            mx1 = fmaxf(mx1, fmaxf(acc[na][2], acc[na][3]));
        }
        mx0 = fmaxf(mx0, __shfl_xor_sync(FULL, mx0, 1));
        mx0 = fmaxf(mx0, __shfl_xor_sync(FULL, mx0, 2));
        mx1 = fmaxf(mx1, __shfl_xor_sync(FULL, mx1, 1));
        mx1 = fmaxf(mx1, __shfl_xor_sync(FULL, mx1, 2));
        if (t == 0) {
            Mred[rr04 + kspl]       = mx0;   // per-warp max; consumed at combine
            Mred[rr04 + 32 + kspl]  = mx1;   // (rr0+8)*4
        }

        // ---- exp2 in fp16 pairs (against OWN warp max) -> P fragments ----
        uint32_t ph[16][2];
#pragma unroll
        for (int na = 0; na < 16; na++) {
            ph[na][0] = h2exp2(pack_h2(acc[na][0] - mx0, acc[na][1] - mx0));
            ph[na][1] = h2exp2(pack_h2(acc[na][2] - mx1, acc[na][3] - mx1));
        }

        // ---- phase 3: O_partial = P @ V  +  row sums via ones-column mma ----
        float oacc[4][4];
#pragma unroll
        for (int na = 0; na < 4; na++)
#pragma unroll
            for (int q = 0; q < 4; q++) oacc[na][q] = 0.f;
        float osum[4] = {0.f, 0.f, 0.f, 0.f};

#pragma unroll
        for (int j = 0; j < 8; j++) {
            const uint32_t pa[4] = { ph[2*j][0], ph[2*j][1], ph[2*j+1][0], ph[2*j+1][1] };
            const int kk = kb0 + 16*j + 2*t;
#pragma unroll
            for (int na = 0; na < 4; na++) {
                const __half* bb = Vth + (na*8 + g)*VT_STR + kk;
                uint32_t bf[2] = { *(const uint32_t*)bb, *(const uint32_t*)(bb + 8) };
                mma_f16(oacc[na], pa, bf);
            }
            mma_f16(osum, pa, onesbf);     // col 0 accumulates row sum
        }
        if (t == 0) {                       // lane t=0 holds col 0 = exact row sum
            Sred[rr04 + kspl]      = osum[0];
            Sred[rr04 + 32 + kspl] = osum[2];
        }

        // ---- store partials ----
        {
            float* op = Op + warp * 640;
#pragma unroll
            for (int na = 0; na < 4; na++) {
                const int c = na*8 + 2*t;
                *(float2*)&op[g*40 + c]     = make_float2(oacc[na][0], oacc[na][1]);
                *(float2*)&op[(g+8)*40 + c] = make_float2(oacc[na][2], oacc[na][3]);
            }
        }
        __syncthreads();

        // ---- combine 4 key-split partials with per-warp-max rescale ----
        {
            const int r  = tid >> 3;            // 0..63
            const int c4 = (tid & 7) * 4;       // 0..28
            const int wb = (r >> 4) * 4;        // ma*4
            const int rl = r & 15;
            const float4 m4 = *(float4*)&Mred[r*4];
            const float M = fmaxf(fmaxf(m4.x, m4.y), fmaxf(m4.z, m4.w));
            const float sc0 = ex2f(m4.x - M);
            const float sc1 = ex2f(m4.y - M);
            const float sc2 = ex2f(m4.z - M);
            const float sc3 = ex2f(m4.w - M);
            const float4 s4 = *(float4*)&Sred[r*4];
            const float sum = s4.x*sc0 + s4.y*sc1 + s4.z*sc2 + s4.w*sc3;

            float4 o = {0.f, 0.f, 0.f, 0.f};
            const float scs[4] = {sc0, sc1, sc2, sc3};
#pragma unroll
            for (int ks = 0; ks < 4; ks++) {
                const float4 p = *(float4*)&Op[(wb + ks)*640 + rl*40 + c4];
                o.x += p.x * scs[ks];
                o.y += p.y * scs[ks];
                o.z += p.z * scs[ks];
                o.w += p.w * scs[ks];
            }
            const float rs = 1.0f / sum;
            uint2 ov;
            ov.x = pack_h2(o.x*rs, o.y*rs);
            ov.y = pack_h2(o.z*rs, o.w*rs);
            *(uint2*)&Ogh[(size_t)(q0 + r)*D_ + c4] = ov;
        }
    }
}

// ---------------- launcher --------------------------------------------------
extern "C" void kernel_launch(void* const* d_in, const int* in_sizes, int n_in,
                              void* d_out, int out_size) {
    const float* h    = (const float*)d_in[0];
    const int*   mask = (const int*)  d_in[1];
    const int*   nc   = (const int*)  d_in[2];
    const float* Wq   = (const float*)d_in[3];
    const float* bq   = (const float*)d_in[4];
    const float* Wk   = (const float*)d_in[5];
    const float* bk   = (const float*)d_in[6];
    const float* Wv   = (const float*)d_in[7];
    const float* bv   = (const float*)d_in[8];
    const float* Wo   = (const float*)d_in[9];
    const float* bo   = (const float*)d_in[10];
    float* out = (float*)d_out;

    cudaFuncSetAttribute(attn_kernel, cudaFuncAttributeMaxDynamicSharedMemorySize,
                         ATTN_SMEM_BYTES);
    cudaFuncSetAttribute(qkv_kernel, cudaFuncAttributeMaxDynamicSharedMemorySize,
                         GEMMH_SMEM_BYTES);
    cudaFuncSetAttribute(oproj_kernel, cudaFuncAttributeMaxDynamicSharedMemorySize,
                         GEMMH_SMEM_BYTES);

    mask_kernel<<<M_/256, 256>>>(mask, nc);
    convh_kernel<<<M_*D_/1024, 256>>>(h);
    convw_kernel<<<256, 256>>>(Wq, Wk, Wv, Wo);
    qkv_kernel<<<dim3(M_/128, D_/128, 3), 256, GEMMH_SMEM_BYTES>>>(bq, bk, bv);
    attn_kernel<<<B_*H_*2, 512, ATTN_SMEM_BYTES>>>();
    oproj_kernel<<<dim3(M_/128, D_/128), 256, GEMMH_SMEM_BYTES>>>(bo, h, out);
}